// round 14
// baseline (speedup 1.0000x reference)
#include <cuda_runtime.h>
#include <cuda_fp16.h>
#include <math.h>
#include <stdint.h>

// Problem constants (fixed by setup_inputs)
#define BB    2
#define HH    16
#define NSEQ  2048
#define EE    1024
#define DD    64
#define CHK   128
#define NCK   16
#define EPSV  1e-6f

// fp16 GEMM tiling: 128x128 CTA tile, BK=64 halves, 8 warps of 32x64.
#define BKH    64
#define SHSTR  72
#define OP_H   (128 * SHSTR)           // halves per operand buffer (9216)
#define OPB    (OP_H * 2)              // bytes per operand buffer (18432)
#define GSMEM  (6 * OPB)               // 110592 bytes (max of both variants)

// chunk_out smem layout (halves)
#define CO_QS   0                      // [128][72]
#define CO_KS   (CO_QS + 128 * 72)     // [128][72]
#define CO_VT   (CO_KS + 128 * 72)     // [64][136] swizzled
#define CO_STZ  (CO_VT + 64 * 136)     // [72][72]
#define CO_AS   (CO_STZ + 72 * 72)     // [128][136]
#define CO_TOT  (CO_AS + 128 * 136)
#define CO_SMEM (CO_TOT * 2)           // 99456 bytes

// chunk_kv smem (halves): kT [64][136] + vT [64][136], swizzled
#define KV_SMEM (2 * 64 * 136 * 2)

// ---------------- scratch (device globals; no allocation allowed) ----------
__device__ __align__(16) __half g_q[BB*HH*NSEQ*DD];
__device__ __align__(16) __half g_k[BB*HH*NSEQ*DD];
__device__ __align__(16) __half g_v[BB*HH*NSEQ*DD];
__device__ __align__(16) __half g_attn[BB*NSEQ*EE];
__device__ float g_S[BB*HH*NCK*DD*DD];                    // per-chunk KtV, [v][d] fp32
__device__ __align__(16) __half g_Sh[BB*HH*NCK*DD*DD];    // prefixed, fp16
__device__ float g_z[BB*HH*NCK*DD];
__device__ __align__(16) __half g_zh[BB*HH*NCK*DD];
__device__ __align__(16) __half g_wh[4 * EE * EE];

// ---------------------------------------------------------------------------
__device__ __forceinline__ void mma_f16(float c[4], const unsigned a[4], const unsigned b[2]) {
    asm volatile(
        "mma.sync.aligned.m16n8k16.row.col.f32.f16.f16.f32 "
        "{%0,%1,%2,%3}, {%4,%5,%6,%7}, {%8,%9}, {%0,%1,%2,%3};\n"
        : "+f"(c[0]), "+f"(c[1]), "+f"(c[2]), "+f"(c[3])
        : "r"(a[0]), "r"(a[1]), "r"(a[2]), "r"(a[3]), "r"(b[0]), "r"(b[1]));
}

__device__ __forceinline__ void ldsm4(unsigned& r0, unsigned& r1,
                                      unsigned& r2, unsigned& r3, uint32_t addr) {
    asm volatile("ldmatrix.sync.aligned.m8n8.x4.shared.b16 {%0,%1,%2,%3}, [%4];"
                 : "=r"(r0), "=r"(r1), "=r"(r2), "=r"(r3) : "r"(addr));
}

__device__ __forceinline__ void cp16s(uint32_t dst, const void* src) {
    asm volatile("cp.async.cg.shared.global [%0], [%1], 16;\n" :: "r"(dst), "l"(src));
}

// swizzled half index into a [64][136] transposed tile: row d, half-col i
__device__ __forceinline__ int swz136(int d, int i) {
    return d * 136 + (((((i >> 1) ^ ((d >> 3) & 7))) << 1) | (i & 1));
}
__device__ __forceinline__ int swz136w(int d, int wi) {
    return d * 136 + (((wi) ^ ((d >> 3) & 7)) << 1);
}

// ---------------------------------------------------------------------------
// Prepass: fp32 -> fp16 for the 4 weight matrices only. grid (1024, 4).
// ---------------------------------------------------------------------------
__global__ void __launch_bounds__(256) conv_w(const float* __restrict__ w0,
                                              const float* __restrict__ w1,
                                              const float* __restrict__ w2,
                                              const float* __restrict__ w3,
                                              __half* __restrict__ wdst) {
    const int z = blockIdx.y;
    const float* src = (z == 0) ? w0 : (z == 1) ? w1 : (z == 2) ? w2 : w3;
    __half* d = wdst + (size_t)z * (EE * EE);
    int i = blockIdx.x * 256 + threadIdx.x;
    float4 v = ((const float4*)src)[i];
    __half2 h0 = __floats2half2_rn(v.x, v.y);
    __half2 h1 = __floats2half2_rn(v.z, v.w);
    ((uint2*)d)[i] = make_uint2(*(unsigned*)&h0, *(unsigned*)&h1);
}

// ---------------------------------------------------------------------------
// Pipelined FP16 NT-GEMM with ldmatrix fragment loads.
// ASRC32: A is fp32 in global; convert to fp16 in-register (same rounding as
// the old conv prepass) and STS into a 2-deep A ring.  Else fp16 cp.async.
// B (pre-converted fp16 weights) always 3-stage cp.async.
// ---------------------------------------------------------------------------
template<bool ASRC32, bool FMAP, bool BHND>
__device__ __forceinline__ void gemm_h_body(const void* __restrict__ Av,
                                            const __half* __restrict__ W,
                                            void* __restrict__ Cv, __half* sm) {
    const int tid = threadIdx.x, lane = tid & 31, warp = tid >> 5;
    const int bm = blockIdx.y * 128, bn = blockIdx.x * 128;
    const int wm = (warp >> 1) * 32, wn = (warp & 1) * 64;
    const int g = lane >> 2, tg = lane & 3;
    const uint32_t sb = (uint32_t)__cvta_generic_to_shared(sm);

    // smem layout (bytes):
    //  ASRC32: bufA0 @0, bufA1 @OPB, bufB j @ (2+j)*OPB  (j=0..2)
    //  fp16-A: stage t%3: A @ t*2*OPB, B @ t*2*OPB + OPB
    const uint32_t bB0 = ASRC32 ? 2 * OPB : 0;

    // ldmatrix lane offsets (in halves)
    const int aoff = ((lane & 7) + (lane & 8)) * SHSTR + ((lane & 16) >> 1);
    const int boff = ((lane & 7) + ((lane & 16) >> 1)) * SHSTR + (lane & 8);

    float acc[2][8][4];
#pragma unroll
    for (int mi = 0; mi < 2; mi++)
#pragma unroll
        for (int nj = 0; nj < 8; nj++)
#pragma unroll
            for (int x = 0; x < 4; x++) acc[mi][nj][x] = 0.f;

    // --- B issue (always cp.async) ---
    auto issueB = [&](int buf, int k0) {
        uint32_t dB = sb + (ASRC32 ? (2 + buf) * OPB : buf * 2 * OPB + OPB);
#pragma unroll
        for (int i = 0; i < 4; i++) {
            int l = tid + i * 256;
            int r = l >> 3, c8 = (l & 7) * 8;
            cp16s(dB + (uint32_t)(r * SHSTR + c8) * 2,
                  W + (size_t)(bn + r) * 1024 + k0 + c8);
        }
    };
    // --- A issue for fp16 source ---
    auto issueA16 = [&](int buf, int k0) {
        uint32_t dA = sb + buf * 2 * OPB;
        const __half* A = (const __half*)Av;
#pragma unroll
        for (int i = 0; i < 4; i++) {
            int l = tid + i * 256;
            int r = l >> 3, c8 = (l & 7) * 8;
            cp16s(dA + (uint32_t)(r * SHSTR + c8) * 2,
                  A + (size_t)(bm + r) * 1024 + k0 + c8);
        }
    };
    // --- A register path for fp32 source ---
    uint2 areg[8];
    auto ldA32 = [&](int k0) {
        const float* A = (const float*)Av;
#pragma unroll
        for (int i = 0; i < 8; i++) {
            int l = tid + i * 256;
            int r = l >> 4, c4 = (l & 15) << 2;
            float4 va = *(const float4*)(A + (size_t)(bm + r) * 1024 + k0 + c4);
            __half2 h0 = __floats2half2_rn(va.x, va.y);
            __half2 h1 = __floats2half2_rn(va.z, va.w);
            areg[i] = make_uint2(*(unsigned*)&h0, *(unsigned*)&h1);
        }
    };
    auto stsA32 = [&](int buf) {
        __half* dA = sm + buf * OP_H;   // halves
#pragma unroll
        for (int i = 0; i < 8; i++) {
            int l = tid + i * 256;
            int r = l >> 4, c4 = (l & 15) << 2;
            *(uint2*)&dA[r * SHSTR + c4] = areg[i];
        }
    };

    // prologue
    if (ASRC32) {
        ldA32(0);
        issueB(0, 0);
        asm volatile("cp.async.commit_group;" ::: "memory");
        issueB(1, BKH);
        asm volatile("cp.async.commit_group;" ::: "memory");
    } else {
        issueA16(0, 0); issueB(0, 0);
        asm volatile("cp.async.commit_group;" ::: "memory");
        issueA16(1, BKH); issueB(1, BKH);
        asm volatile("cp.async.commit_group;" ::: "memory");
    }

    for (int t = 0; t < 16; t++) {
        if (ASRC32) {
            stsA32(t & 1);                       // safe: last reader was compute(t-2)
            if (t + 1 < 16) ldA32((t + 1) * BKH);
        }
        asm volatile("cp.async.wait_group 1;" ::: "memory");
        __syncthreads();
        if (t + 2 < 16) {
            if (ASRC32) issueB((t + 2) % 3, (t + 2) * BKH);
            else { issueA16((t + 2) % 3, (t + 2) * BKH); issueB((t + 2) % 3, (t + 2) * BKH); }
        }
        asm volatile("cp.async.commit_group;" ::: "memory");

        const uint32_t sA = ASRC32 ? sb + (t & 1) * OPB
                                   : sb + (t % 3) * 2 * OPB;
        const uint32_t sB = ASRC32 ? sb + bB0 + (t % 3) * OPB
                                   : sA + OPB;
#pragma unroll
        for (int ks = 0; ks < 4; ks++) {
            const int kb = ks * 16;
            unsigned a[2][4], b[8][2];
#pragma unroll
            for (int mi = 0; mi < 2; mi++) {
                uint32_t ad = sA + (uint32_t)(((wm + mi * 16) * SHSTR + kb) + aoff) * 2;
                ldsm4(a[mi][0], a[mi][1], a[mi][2], a[mi][3], ad);
            }
#pragma unroll
            for (int p = 0; p < 4; p++) {
                uint32_t bd = sB + (uint32_t)(((wn + p * 16) * SHSTR + kb) + boff) * 2;
                ldsm4(b[2*p][0], b[2*p][1], b[2*p+1][0], b[2*p+1][1], bd);
            }
#pragma unroll
            for (int mi = 0; mi < 2; mi++)
#pragma unroll
                for (int nj = 0; nj < 8; nj++)
                    mma_f16(acc[mi][nj], a[mi], b[nj]);
        }
    }

#pragma unroll
    for (int mi = 0; mi < 2; mi++) {
#pragma unroll
        for (int nj = 0; nj < 8; nj++) {
            int row0 = bm + wm + mi * 16 + g;
            int col0 = bn + wn + nj * 8 + 2 * tg;
#pragma unroll
            for (int half_ = 0; half_ < 2; half_++) {
                int row = row0 + half_ * 8;
                float v0 = acc[mi][nj][half_ * 2 + 0];
                float v1 = acc[mi][nj][half_ * 2 + 1];
                if (FMAP) {
                    v0 = (v0 > 0.f) ? (v0 + 1.f) : __expf(v0);
                    v1 = (v1 > 0.f) ? (v1 + 1.f) : __expf(v1);
                }
                if (BHND) {
                    int bb = row >> 11, n = row & 2047;
                    int h = col0 >> 6, d = col0 & 63;
                    size_t idx = ((((size_t)bb * HH + h) * NSEQ + n) * DD + d);
                    __half2 hv = __floats2half2_rn(v0, v1);
                    *(__half2*)&((__half*)Cv)[idx] = hv;
                } else {
                    size_t idx = (size_t)row * 1024 + col0;
                    *(float2*)&((float*)Cv)[idx] = make_float2(v0, v1);
                }
            }
        }
    }
}

__global__ void __launch_bounds__(256, 2) gemm_h_qkv(const float* __restrict__ Q,
                                                     const float* __restrict__ K,
                                                     const float* __restrict__ V,
                                                     const __half* __restrict__ WH,
                                                     __half* __restrict__ qb,
                                                     __half* __restrict__ kb,
                                                     __half* __restrict__ vb) {
    extern __shared__ __half smh[];
    const int z = blockIdx.z;
    const float* A = (z == 0) ? Q : (z == 1) ? K : V;
    const __half* W = WH + (size_t)z * (EE * EE);
    __half* C = (z == 0) ? qb : (z == 1) ? kb : vb;
    if (z < 2) gemm_h_body<true, true,  true>(A, W, C, smh);
    else       gemm_h_body<true, false, true>(A, W, C, smh);
}

__global__ void __launch_bounds__(256, 2) gemm_h_out(const __half* __restrict__ A,
                                                     const __half* __restrict__ WH,
                                                     float* __restrict__ C) {
    extern __shared__ __half smh[];
    gemm_h_body<false, false, false>(A, WH + (size_t)3 * EE * EE, C, smh);
}

// ---------------------------------------------------------------------------
// Pass 1 (fp16 mma): ST_c[v][d] = sum_i k[i,d]*v[i,v] (fp32, transposed),
// z_c[d] = sum_i k[i,d]. Swizzled smem transposes (conflict-free).
// ---------------------------------------------------------------------------
__global__ void __launch_bounds__(256) chunk_kv_h(const __half* __restrict__ k,
                                                  const __half* __restrict__ v,
                                                  float* __restrict__ S,
                                                  float* __restrict__ z) {
    extern __shared__ __half smh[];
    __half* kT = smh;              // [64][136] swizzled
    __half* vT = smh + 64 * 136;
    const int blk = blockIdx.x;
    const int c = blk & 15, bh = blk >> 4;
    const int tid = threadIdx.x;
    const int lane = tid & 31, warp = tid >> 5;
    const int g = lane >> 2, tg = lane & 3;

    const size_t base = ((size_t)bh * NSEQ + (size_t)c * CHK) * DD;
    for (int idx = tid; idx < 1024; idx += 256) {
        int i = idx >> 3, d8 = (idx & 7) * 8;
        uint4 kk = *(const uint4*)&k[base + (size_t)i * 64 + d8];
        uint4 vv = *(const uint4*)&v[base + (size_t)i * 64 + d8];
        const __half* kh = (const __half*)&kk;
        const __half* vh = (const __half*)&vv;
#pragma unroll
        for (int j = 0; j < 8; j++) {
            kT[swz136(d8 + j, i)] = kh[j];
            vT[swz136(d8 + j, i)] = vh[j];
        }
    }
    __syncthreads();

    {
        int d = tid >> 2, quad = tid & 3;
        float s = 0.f;
#pragma unroll
        for (int wi = 0; wi < 16; wi++) {
            unsigned u = *(const unsigned*)&kT[swz136w(d, quad * 16 + wi)];
            __half2 h = *(__half2*)&u;
            s += __half2float(h.x) + __half2float(h.y);
        }
        s += __shfl_xor_sync(0xffffffffu, s, 1);
        s += __shfl_xor_sync(0xffffffffu, s, 2);
        if (quad == 0) z[(size_t)blk * 64 + d] = s;
    }

    const int wm = (warp & 1) * 32, wn = (warp >> 1) * 16;
    float acc[2][2][4];
#pragma unroll
    for (int mi = 0; mi < 2; mi++)
#pragma unroll
        for (int nj = 0; nj < 2; nj++)
#pragma unroll
            for (int x = 0; x < 4; x++) acc[mi][nj][x] = 0.f;

#pragma unroll
    for (int kb = 0; kb < 128; kb += 16) {
        const int w0 = kb >> 1;
        unsigned a[2][4], b[2][2];
#pragma unroll
        for (int mi = 0; mi < 2; mi++) {
            int m = wm + mi * 16 + g;
            a[mi][0] = *(const unsigned*)&kT[swz136w(m,     w0 + tg)];
            a[mi][1] = *(const unsigned*)&kT[swz136w(m + 8, w0 + tg)];
            a[mi][2] = *(const unsigned*)&kT[swz136w(m,     w0 + tg + 4)];
            a[mi][3] = *(const unsigned*)&kT[swz136w(m + 8, w0 + tg + 4)];
        }
#pragma unroll
        for (int nj = 0; nj < 2; nj++) {
            int n = wn + nj * 8 + g;
            b[nj][0] = *(const unsigned*)&vT[swz136w(n, w0 + tg)];
            b[nj][1] = *(const unsigned*)&vT[swz136w(n, w0 + tg + 4)];
        }
#pragma unroll
        for (int mi = 0; mi < 2; mi++)
#pragma unroll
            for (int nj = 0; nj < 2; nj++)
                mma_f16(acc[mi][nj], a[mi], b[nj]);
    }

    float* Sc = S + (size_t)blk * 4096;
#pragma unroll
    for (int mi = 0; mi < 2; mi++) {
#pragma unroll
        for (int nj = 0; nj < 2; nj++) {
            int d0 = wm + mi * 16 + g;
            int v0 = wn + nj * 8 + 2 * tg;
            Sc[(v0)     * 64 + d0    ] = acc[mi][nj][0];
            Sc[(v0 + 1) * 64 + d0    ] = acc[mi][nj][1];
            Sc[(v0)     * 64 + d0 + 8] = acc[mi][nj][2];
            Sc[(v0 + 1) * 64 + d0 + 8] = acc[mi][nj][3];
        }
    }
}

// ---------------------------------------------------------------------------
// Pass 2: exclusive prefix (causal) / total (non-causal); reg-batched loads.
// ---------------------------------------------------------------------------
__global__ void __launch_bounds__(256) prefix_k(const float* __restrict__ S,
                                                const float* __restrict__ z,
                                                __half* __restrict__ Sh,
                                                __half* __restrict__ zh,
                                                const int* __restrict__ causal) {
    const int bh = blockIdx.x;
    const int e = blockIdx.y * 256 + threadIdx.x;
    const int caus = *causal;
    {
        float t[NCK];
#pragma unroll
        for (int c = 0; c < NCK; c++)
            t[c] = S[((size_t)bh * NCK + c) * 4096 + e];
        if (caus) {
            float run = 0.f;
#pragma unroll
            for (int c = 0; c < NCK; c++) {
                Sh[((size_t)bh * NCK + c) * 4096 + e] = __float2half_rn(run);
                run += t[c];
            }
        } else {
            float run = 0.f;
#pragma unroll
            for (int c = 0; c < NCK; c++) run += t[c];
            __half hr = __float2half_rn(run);
#pragma unroll
            for (int c = 0; c < NCK; c++)
                Sh[((size_t)bh * NCK + c) * 4096 + e] = hr;
        }
    }
    if (blockIdx.y == 0 && threadIdx.x < 64) {
        int d = threadIdx.x;
        float t[NCK];
#pragma unroll
        for (int c = 0; c < NCK; c++)
            t[c] = z[((size_t)bh * NCK + c) * 64 + d];
        if (caus) {
            float run = 0.f;
#pragma unroll
            for (int c = 0; c < NCK; c++) {
                zh[((size_t)bh * NCK + c) * 64 + d] = __float2half_rn(run);
                run += t[c];
            }
        } else {
            float run = 0.f;
#pragma unroll
            for (int c = 0; c < NCK; c++) run += t[c];
            __half hr = __float2half_rn(run);
#pragma unroll
            for (int c = 0; c < NCK; c++)
                zh[((size_t)bh * NCK + c) * 64 + d] = hr;
        }
    }
}

// ---------------------------------------------------------------------------
// Pass 3 (fp16 mma): per-chunk output. Triangular skips + swizzled vT.
// ---------------------------------------------------------------------------
__global__ void __launch_bounds__(256, 2) chunk_out_h(const __half* __restrict__ q,
                                                      const __half* __restrict__ k,
                                                      const __half* __restrict__ v,
                                                      const __half* __restrict__ Sh,
                                                      const __half* __restrict__ zh,
                                                      const int* __restrict__ causal,
                                                      __half* __restrict__ out) {
    extern __shared__ __half smh[];
    __half* qs  = smh + CO_QS;
    __half* ks  = smh + CO_KS;
    __half* vT  = smh + CO_VT;
    __half* STz = smh + CO_STZ;
    __half* Ash = smh + CO_AS;

    const int blk = blockIdx.x;
    const int c = blk & 15, bh = blk >> 4;
    const int b = bh >> 4, h = bh & 15;
    const int tid = threadIdx.x;
    const int lane = tid & 31, warp = tid >> 5;
    const int g = lane >> 2, tg = lane & 3;
    const int caus = *causal;
    const int m0 = warp * 16;

    const size_t base = ((size_t)bh * NSEQ + (size_t)c * CHK) * DD;
    for (int idx = tid; idx < 1024; idx += 256) {
        int i = idx >> 3, d8 = (idx & 7) * 8;
        *(uint4*)&qs[i * 72 + d8] = *(const uint4*)&q[base + (size_t)i * 64 + d8];
        *(uint4*)&ks[i * 72 + d8] = *(const uint4*)&k[base + (size_t)i * 64 + d8];
        uint4 vv = *(const uint4*)&v[base + (size_t)i * 64 + d8];
        const __half* vh = (const __half*)&vv;
#pragma unroll
        for (int j = 0; j < 8; j++) vT[swz136(d8 + j, i)] = vh[j];
    }
    for (int idx = tid; idx < 512; idx += 256) {
        int j = idx >> 3, d8 = (idx & 7) * 8;
        *(uint4*)&STz[j * 72 + d8] =
            *(const uint4*)&Sh[(size_t)blk * 4096 + (size_t)j * 64 + d8];
    }
    if (tid < 64) STz[64 * 72 + tid] = zh[(size_t)blk * 64 + tid];
    for (int idx = tid; idx < 7 * 72; idx += 256) STz[65 * 72 + idx] = __float2half_rn(0.f);
    __syncthreads();

    const int r0 = m0 + g, r1 = r0 + 8;
    float den0 = 0.f, den1 = 0.f;

    if (caus) {
        const int njmax = 2 * warp + 1;
#pragma unroll
        for (int h2 = 0; h2 < 2; h2++) {
            if (h2 * 8 <= njmax) {
                float accA[8][4];
#pragma unroll
                for (int nj = 0; nj < 8; nj++)
#pragma unroll
                    for (int x = 0; x < 4; x++) accA[nj][x] = 0.f;
#pragma unroll
                for (int kb = 0; kb < 64; kb += 16) {
                    unsigned a[4];
                    a[0] = *(const unsigned*)&qs[(r0) * 72 + kb + 2 * tg];
                    a[1] = *(const unsigned*)&qs[(r1) * 72 + kb + 2 * tg];
                    a[2] = *(const unsigned*)&qs[(r0) * 72 + kb + 2 * tg + 8];
                    a[3] = *(const unsigned*)&qs[(r1) * 72 + kb + 2 * tg + 8];
#pragma unroll
                    for (int nj = 0; nj < 8; nj++) {
                        int njg = h2 * 8 + nj;
                        if (njg <= njmax) {
                            unsigned bf[2];
                            bf[0] = *(const unsigned*)&ks[(njg * 8 + g) * 72 + kb + 2 * tg];
                            bf[1] = *(const unsigned*)&ks[(njg * 8 + g) * 72 + kb + 2 * tg + 8];
                            mma_f16(accA[nj], a, bf);
                        }
                    }
                }
#pragma unroll
                for (int nj = 0; nj < 8; nj++) {
                    int njg = h2 * 8 + nj;
                    if (njg <= njmax) {
                        int c0 = njg * 8 + 2 * tg;
                        float x00 = (c0     <= r0) ? accA[nj][0] : 0.f;
                        float x01 = (c0 + 1 <= r0) ? accA[nj][1] : 0.f;
                        float x10 = (c0     <= r1) ? accA[nj][2] : 0.f;
                        float x11 = (c0 + 1 <= r1) ? accA[nj][3] : 0.f;
                        den0 += x00 + x01;
                        den1 += x10 + x11;
                        *(__half2*)&Ash[r0 * 136 + c0] = __floats2half2_rn(x00, x01);
                        *(__half2*)&Ash[r1 * 136 + c0] = __floats2half2_rn(x10, x11);
                    }
                }
            }
        }
        den0 += __shfl_xor_sync(0xffffffffu, den0, 1);
        den0 += __shfl_xor_sync(0xffffffffu, den0, 2);
        den1 += __shfl_xor_sync(0xffffffffu, den1, 1);
        den1 += __shfl_xor_sync(0xffffffffu, den1, 2);
        __syncwarp();
    }

    float acc[9][4];
#pragma unroll
    for (int nj = 0; nj < 9; nj++)
#pragma unroll
        for (int x = 0; x < 4; x++) acc[nj][x] = 0.f;

#pragma unroll
    for (int kb = 0; kb < 64; kb += 16) {
        unsigned a[4];
        a[0] = *(const unsigned*)&qs[(r0) * 72 + kb + 2 * tg];
        a[1] = *(const unsigned*)&qs[(r1) * 72 + kb + 2 * tg];
        a[2] = *(const unsigned*)&qs[(r0) * 72 + kb + 2 * tg + 8];
        a[3] = *(const unsigned*)&qs[(r1) * 72 + kb + 2 * tg + 8];
#pragma unroll
        for (int nj = 0; nj < 9; nj++) {
            unsigned bf[2];
            bf[0] = *(const unsigned*)&STz[(nj * 8 + g) * 72 + kb + 2 * tg];
            bf[1] = *(const unsigned*)&STz[(nj * 8 + g) * 72 + kb + 2 * tg + 8];
            mma_f16(acc[nj], a, bf);
        }
    }
    if (caus) {
#pragma unroll
        for (int kb = 0; kb < 128; kb += 16) {
            if ((kb >> 4) <= warp) {
                const int w0 = kb >> 1;
                unsigned a[4];
                a[0] = *(const unsigned*)&Ash[(r0) * 136 + kb + 2 * tg];
                a[1] = *(const unsigned*)&Ash[(r1) * 136 + kb + 2 * tg];
                a[2] = *(const unsigned*)&Ash[(r0) * 136 + kb + 2 * tg + 8];
                a[3] = *(const unsigned*)&Ash[(r1) * 136 + kb + 2 * tg + 8];
#pragma unroll
                for (int nj = 0; nj < 8; nj++) {
                    int n = nj * 8 + g;
                    unsigned bf[2];
                    bf[0] = *(const unsigned*)&vT[swz136w(n, w0 + tg)];
                    bf[1] = *(const unsigned*)&vT[swz136w(n, w0 + tg + 4)];
                    mma_f16(acc[nj], a, bf);
                }
            }
        }
    }

    float qz0 = __shfl_sync(0xffffffffu, acc[8][0], (lane & ~3));
    float qz1 = __shfl_sync(0xffffffffu, acc[8][2], (lane & ~3));
    float inv0 = 1.f / (den0 + qz0 + EPSV);
    float inv1 = 1.f / (den1 + qz1 + EPSV);

#pragma unroll
    for (int nj = 0; nj < 8; nj++) {
        int col = h * 64 + nj * 8 + 2 * tg;
        size_t o0 = ((size_t)b * NSEQ + (size_t)c * CHK + r0) * EE + col;
        size_t o1 = ((size_t)b * NSEQ + (size_t)c * CHK + r1) * EE + col;
        *(__half2*)&out[o0] = __floats2half2_rn(acc[nj][0] * inv0, acc[nj][1] * inv0);
        *(__half2*)&out[o1] = __floats2half2_rn(acc[nj][2] * inv1, acc[nj][3] * inv1);
    }
}

// ---------------------------------------------------------------------------
extern "C" void kernel_launch(void* const* d_in, const int* in_sizes, int n_in,
                              void* d_out, int out_size) {
    const float* Q  = (const float*)d_in[0];
    const float* K  = (const float*)d_in[1];
    const float* V  = (const float*)d_in[2];
    const float* Wq = (const float*)d_in[3];
    const float* Wk = (const float*)d_in[4];
    const float* Wv = (const float*)d_in[5];
    const float* Wo = (const float*)d_in[6];
    const int* causal = (const int*)d_in[7];
    float* out = (float*)d_out;

    __half *qb, *kb, *vb, *ab, *wh, *Shb, *zhb;
    float *Sb, *zb;
    cudaGetSymbolAddress((void**)&qb, g_q);
    cudaGetSymbolAddress((void**)&kb, g_k);
    cudaGetSymbolAddress((void**)&vb, g_v);
    cudaGetSymbolAddress((void**)&ab, g_attn);
    cudaGetSymbolAddress((void**)&Sb, g_S);
    cudaGetSymbolAddress((void**)&zb, g_z);
    cudaGetSymbolAddress((void**)&Shb, g_Sh);
    cudaGetSymbolAddress((void**)&zhb, g_zh);
    cudaGetSymbolAddress((void**)&wh, g_wh);

    cudaFuncSetAttribute(gemm_h_qkv, cudaFuncAttributeMaxDynamicSharedMemorySize, GSMEM);
    cudaFuncSetAttribute(gemm_h_out, cudaFuncAttributeMaxDynamicSharedMemorySize, GSMEM);
    cudaFuncSetAttribute(chunk_kv_h, cudaFuncAttributeMaxDynamicSharedMemorySize, KV_SMEM);
    cudaFuncSetAttribute(chunk_out_h, cudaFuncAttributeMaxDynamicSharedMemorySize, CO_SMEM);

    conv_w<<<dim3(1024, 4), 256>>>(Wq, Wk, Wv, Wo, wh);

    dim3 gq(8, 32, 3);
    gemm_h_qkv<<<gq, 256, GSMEM>>>(Q, K, V, wh, qb, kb, vb);

    chunk_kv_h<<<BB * HH * NCK, 256, KV_SMEM>>>(kb, vb, Sb, zb);
    prefix_k<<<dim3(BB * HH, 16), 256>>>(Sb, zb, Shb, zhb, causal);
    chunk_out_h<<<BB * HH * NCK, 256, CO_SMEM>>>(qb, kb, vb, Shb, zhb, causal, ab);

    dim3 go(8, 32);
    gemm_h_out<<<go, 256, GSMEM>>>(ab, wh, out);
}

// round 15
// speedup vs baseline: 1.5219x; 1.5219x over previous
#include <cuda_runtime.h>
#include <cuda_fp16.h>
#include <math.h>
#include <stdint.h>

// Problem constants (fixed by setup_inputs)
#define BB    2
#define HH    16
#define NSEQ  2048
#define EE    1024
#define DD    64
#define CHK   128
#define NCK   16
#define EPSV  1e-6f

// fp16 GEMM tiling: 128x128 CTA tile, BK=64 halves, 3-stage cp.async
#define BKH    64
#define SHSTR  72
#define OP_H   (128 * SHSTR)
#define STG_H  (2 * OP_H)
#define STG_B  (STG_H * 2)
#define NSTG   3
#define GSMEM  (NSTG * STG_B)          // 110592 bytes

// chunk_out smem layout (halves)
#define CO_QS   0                      // [128][72]
#define CO_KS   (CO_QS + 128 * 72)     // [128][72]
#define CO_VT   (CO_KS + 128 * 72)     // [64][136] swizzled
#define CO_STZ  (CO_VT + 64 * 136)     // [72][72]
#define CO_AS   (CO_STZ + 72 * 72)     // [128][136]
#define CO_TOT  (CO_AS + 128 * 136)
#define CO_SMEM (CO_TOT * 2)           // 99456 bytes

// chunk_kv smem (halves): kT [64][136] + vT [64][136], swizzled
#define KV_SMEM (2 * 64 * 136 * 2)

// ---------------- scratch (device globals; no allocation allowed) ----------
__device__ __align__(16) __half g_q[BB*HH*NSEQ*DD];
__device__ __align__(16) __half g_k[BB*HH*NSEQ*DD];
__device__ __align__(16) __half g_v[BB*HH*NSEQ*DD];
__device__ __align__(16) __half g_attn[BB*NSEQ*EE];
__device__ float g_S[BB*HH*NCK*DD*DD];                    // per-chunk KtV, [v][d] fp32
__device__ __align__(16) __half g_Sh[BB*HH*NCK*DD*DD];    // prefixed, fp16
__device__ float g_z[BB*HH*NCK*DD];
__device__ __align__(16) __half g_zh[BB*HH*NCK*DD];
__device__ __align__(16) __half g_wh[4 * EE * EE];
__device__ __align__(16) __half g_xh[3 * BB * NSEQ * EE];

// ---------------------------------------------------------------------------
__device__ __forceinline__ void mma_f16(float c[4], const unsigned a[4], const unsigned b[2]) {
    asm volatile(
        "mma.sync.aligned.m16n8k16.row.col.f32.f16.f16.f32 "
        "{%0,%1,%2,%3}, {%4,%5,%6,%7}, {%8,%9}, {%0,%1,%2,%3};\n"
        : "+f"(c[0]), "+f"(c[1]), "+f"(c[2]), "+f"(c[3])
        : "r"(a[0]), "r"(a[1]), "r"(a[2]), "r"(a[3]), "r"(b[0]), "r"(b[1]));
}

__device__ __forceinline__ void ldsm4(unsigned& r0, unsigned& r1,
                                      unsigned& r2, unsigned& r3, uint32_t addr) {
    asm volatile("ldmatrix.sync.aligned.m8n8.x4.shared.b16 {%0,%1,%2,%3}, [%4];"
                 : "=r"(r0), "=r"(r1), "=r"(r2), "=r"(r3) : "r"(addr));
}

__device__ __forceinline__ void cp16s(uint32_t dst, const void* src) {
    asm volatile("cp.async.cg.shared.global [%0], [%1], 16;\n" :: "r"(dst), "l"(src));
}

// swizzled half index into a [64][136] transposed tile: row d, half-col i
__device__ __forceinline__ int swz136(int d, int i) {
    return d * 136 + (((((i >> 1) ^ ((d >> 3) & 7))) << 1) | (i & 1));
}
// word-aligned variant: row d, word wi (2 halves)
__device__ __forceinline__ int swz136w(int d, int wi) {
    return d * 136 + (((wi) ^ ((d >> 3) & 7)) << 1);
}

// ---------------------------------------------------------------------------
// Fused prepass: fp32 -> fp16 for 4 weights (z=0..3) and 3 inputs (z=4..6).
// grid (4096, 7); weights use only first 1024 x-blocks.
// ---------------------------------------------------------------------------
__global__ void __launch_bounds__(256) conv_all(const float* __restrict__ w0,
                                                const float* __restrict__ w1,
                                                const float* __restrict__ w2,
                                                const float* __restrict__ w3,
                                                const float* __restrict__ x0,
                                                const float* __restrict__ x1,
                                                const float* __restrict__ x2,
                                                __half* __restrict__ wdst,
                                                __half* __restrict__ xdst) {
    const int z = blockIdx.y;
    const float* src;
    __half* d;
    if (z < 4) {
        if (blockIdx.x >= 1024) return;
        src = (z == 0) ? w0 : (z == 1) ? w1 : (z == 2) ? w2 : w3;
        d = wdst + (size_t)z * (EE * EE);
    } else {
        src = (z == 4) ? x0 : (z == 5) ? x1 : x2;
        d = xdst + (size_t)(z - 4) * (BB * NSEQ * EE);
    }
    int i = blockIdx.x * 256 + threadIdx.x;
    float4 v = ((const float4*)src)[i];
    __half2 h0 = __floats2half2_rn(v.x, v.y);
    __half2 h1 = __floats2half2_rn(v.z, v.w);
    ((uint2*)d)[i] = make_uint2(*(unsigned*)&h0, *(unsigned*)&h1);
}

// ---------------------------------------------------------------------------
// Pipelined FP16 NT-GEMM with ldmatrix fragment loads.
// ---------------------------------------------------------------------------
template<bool FMAP, bool BHND>
__device__ __forceinline__ void gemm_h_body(const __half* __restrict__ A,
                                            const __half* __restrict__ W,
                                            void* __restrict__ Cv, __half* sm) {
    const int tid = threadIdx.x, lane = tid & 31, warp = tid >> 5;
    const int bm = blockIdx.y * 128, bn = blockIdx.x * 128;
    const int wm = (warp >> 1) * 32, wn = (warp & 1) * 64;
    const int g = lane >> 2, tg = lane & 3;
    const uint32_t sb = (uint32_t)__cvta_generic_to_shared(sm);

    // ldmatrix lane offsets (in halves)
    const int aoff = ((lane & 7) + (lane & 8)) * SHSTR + ((lane & 16) >> 1);
    const int boff = ((lane & 7) + ((lane & 16) >> 1)) * SHSTR + (lane & 8);

    float acc[2][8][4];
#pragma unroll
    for (int mi = 0; mi < 2; mi++)
#pragma unroll
        for (int nj = 0; nj < 8; nj++)
#pragma unroll
            for (int x = 0; x < 4; x++) acc[mi][nj][x] = 0.f;

    auto issue = [&](int buf, int k0) {
        uint32_t dA = sb + buf * STG_B;
        uint32_t dB = dA + OP_H * 2;
#pragma unroll
        for (int i = 0; i < 4; i++) {
            int l = tid + i * 256;
            int r = l >> 3, c8 = (l & 7) * 8;
            uint32_t so = (uint32_t)(r * SHSTR + c8) * 2;
            cp16s(dA + so, A + (size_t)(bm + r) * 1024 + k0 + c8);
            cp16s(dB + so, W + (size_t)(bn + r) * 1024 + k0 + c8);
        }
    };

    issue(0, 0);
    asm volatile("cp.async.commit_group;" ::: "memory");
    issue(1, BKH);
    asm volatile("cp.async.commit_group;" ::: "memory");

    for (int t = 0; t < 16; t++) {
        asm volatile("cp.async.wait_group 1;" ::: "memory");
        __syncthreads();
        if (t + 2 < 16) issue((t + 2) % NSTG, (t + 2) * BKH);
        asm volatile("cp.async.commit_group;" ::: "memory");

        const uint32_t sA = sb + (t % NSTG) * STG_B;
        const uint32_t sB = sA + OP_H * 2;
#pragma unroll
        for (int ks = 0; ks < 4; ks++) {
            const int kb = ks * 16;
            unsigned a[2][4], b[8][2];
#pragma unroll
            for (int mi = 0; mi < 2; mi++) {
                uint32_t ad = sA + (uint32_t)(((wm + mi * 16) * SHSTR + kb) + aoff) * 2;
                ldsm4(a[mi][0], a[mi][1], a[mi][2], a[mi][3], ad);
            }
#pragma unroll
            for (int p = 0; p < 4; p++) {
                uint32_t bd = sB + (uint32_t)(((wn + p * 16) * SHSTR + kb) + boff) * 2;
                ldsm4(b[2*p][0], b[2*p][1], b[2*p+1][0], b[2*p+1][1], bd);
            }
#pragma unroll
            for (int mi = 0; mi < 2; mi++)
#pragma unroll
                for (int nj = 0; nj < 8; nj++)
                    mma_f16(acc[mi][nj], a[mi], b[nj]);
        }
    }

#pragma unroll
    for (int mi = 0; mi < 2; mi++) {
#pragma unroll
        for (int nj = 0; nj < 8; nj++) {
            int row0 = bm + wm + mi * 16 + g;
            int col0 = bn + wn + nj * 8 + 2 * tg;
#pragma unroll
            for (int half_ = 0; half_ < 2; half_++) {
                int row = row0 + half_ * 8;
                float v0 = acc[mi][nj][half_ * 2 + 0];
                float v1 = acc[mi][nj][half_ * 2 + 1];
                if (FMAP) {
                    v0 = (v0 > 0.f) ? (v0 + 1.f) : expf(v0);
                    v1 = (v1 > 0.f) ? (v1 + 1.f) : expf(v1);
                }
                if (BHND) {
                    int bb = row >> 11, n = row & 2047;
                    int h = col0 >> 6, d = col0 & 63;
                    size_t idx = ((((size_t)bb * HH + h) * NSEQ + n) * DD + d);
                    __half2 hv = __floats2half2_rn(v0, v1);
                    *(__half2*)&((__half*)Cv)[idx] = hv;
                } else {
                    size_t idx = (size_t)row * 1024 + col0;
                    *(float2*)&((float*)Cv)[idx] = make_float2(v0, v1);
                }
            }
        }
    }
}

__global__ void __launch_bounds__(256, 2) gemm_h_qkv(const __half* __restrict__ XH,
                                                     const __half* __restrict__ WH,
                                                     __half* __restrict__ qb,
                                                     __half* __restrict__ kb,
                                                     __half* __restrict__ vb) {
    extern __shared__ __half smh[];
    const int z = blockIdx.z;
    const __half* A = XH + (size_t)z * (BB * NSEQ * EE);
    const __half* W = WH + (size_t)z * (EE * EE);
    __half* C = (z == 0) ? qb : (z == 1) ? kb : vb;
    if (z < 2) gemm_h_body<true,  true>(A, W, C, smh);
    else       gemm_h_body<false, true>(A, W, C, smh);
}

__global__ void __launch_bounds__(256, 2) gemm_h_out(const __half* __restrict__ A,
                                                     const __half* __restrict__ WH,
                                                     float* __restrict__ C) {
    extern __shared__ __half smh[];
    gemm_h_body<false, false>(A, WH + (size_t)3 * EE * EE, C, smh);
}

// ---------------------------------------------------------------------------
// Pass 1 (fp16 mma): ST_c[v][d] = sum_i k[i,d]*v[i,v] (fp32, transposed),
// z_c[d] = sum_i k[i,d]. Swizzled smem transposes (conflict-free).
// ---------------------------------------------------------------------------
__global__ void __launch_bounds__(256) chunk_kv_h(const __half* __restrict__ k,
                                                  const __half* __restrict__ v,
                                                  float* __restrict__ S,
                                                  float* __restrict__ z) {
    extern __shared__ __half smh[];
    __half* kT = smh;              // [64][136] swizzled
    __half* vT = smh + 64 * 136;
    const int blk = blockIdx.x;
    const int c = blk & 15, bh = blk >> 4;
    const int tid = threadIdx.x;
    const int lane = tid & 31, warp = tid >> 5;
    const int g = lane >> 2, tg = lane & 3;

    const size_t base = ((size_t)bh * NSEQ + (size_t)c * CHK) * DD;
    for (int idx = tid; idx < 1024; idx += 256) {
        int i = idx >> 3, d8 = (idx & 7) * 8;
        uint4 kk = *(const uint4*)&k[base + (size_t)i * 64 + d8];
        uint4 vv = *(const uint4*)&v[base + (size_t)i * 64 + d8];
        const __half* kh = (const __half*)&kk;
        const __half* vh = (const __half*)&vv;
#pragma unroll
        for (int j = 0; j < 8; j++) {
            kT[swz136(d8 + j, i)] = kh[j];
            vT[swz136(d8 + j, i)] = vh[j];
        }
    }
    __syncthreads();

    // z: 4 lanes per d, word loads
    {
        int d = tid >> 2, quad = tid & 3;
        float s = 0.f;
#pragma unroll
        for (int wi = 0; wi < 16; wi++) {
            unsigned u = *(const unsigned*)&kT[swz136w(d, quad * 16 + wi)];
            __half2 h = *(__half2*)&u;
            s += __half2float(h.x) + __half2float(h.y);
        }
        s += __shfl_xor_sync(0xffffffffu, s, 1);
        s += __shfl_xor_sync(0xffffffffu, s, 2);
        if (quad == 0) z[(size_t)blk * 64 + d] = s;
    }

    const int wm = (warp & 1) * 32, wn = (warp >> 1) * 16;
    float acc[2][2][4];
#pragma unroll
    for (int mi = 0; mi < 2; mi++)
#pragma unroll
        for (int nj = 0; nj < 2; nj++)
#pragma unroll
            for (int x = 0; x < 4; x++) acc[mi][nj][x] = 0.f;

#pragma unroll
    for (int kb = 0; kb < 128; kb += 16) {
        const int w0 = kb >> 1;    // word base
        unsigned a[2][4], b[2][2];
#pragma unroll
        for (int mi = 0; mi < 2; mi++) {
            int m = wm + mi * 16 + g;
            a[mi][0] = *(const unsigned*)&kT[swz136w(m,     w0 + tg)];
            a[mi][1] = *(const unsigned*)&kT[swz136w(m + 8, w0 + tg)];
            a[mi][2] = *(const unsigned*)&kT[swz136w(m,     w0 + tg + 4)];
            a[mi][3] = *(const unsigned*)&kT[swz136w(m + 8, w0 + tg + 4)];
        }
#pragma unroll
        for (int nj = 0; nj < 2; nj++) {
            int n = wn + nj * 8 + g;
            b[nj][0] = *(const unsigned*)&vT[swz136w(n, w0 + tg)];
            b[nj][1] = *(const unsigned*)&vT[swz136w(n, w0 + tg + 4)];
        }
#pragma unroll
        for (int mi = 0; mi < 2; mi++)
#pragma unroll
            for (int nj = 0; nj < 2; nj++)
                mma_f16(acc[mi][nj], a[mi], b[nj]);
    }

    float* Sc = S + (size_t)blk * 4096;
#pragma unroll
    for (int mi = 0; mi < 2; mi++) {
#pragma unroll
        for (int nj = 0; nj < 2; nj++) {
            int d0 = wm + mi * 16 + g;
            int v0 = wn + nj * 8 + 2 * tg;
            Sc[(v0)     * 64 + d0    ] = acc[mi][nj][0];
            Sc[(v0 + 1) * 64 + d0    ] = acc[mi][nj][1];
            Sc[(v0)     * 64 + d0 + 8] = acc[mi][nj][2];
            Sc[(v0 + 1) * 64 + d0 + 8] = acc[mi][nj][3];
        }
    }
}

// ---------------------------------------------------------------------------
// Pass 2: exclusive prefix (causal) / total (non-causal); fp32 scan in regs,
// fp16 output for chunk_out. grid (32,16).
// ---------------------------------------------------------------------------
__global__ void __launch_bounds__(256) prefix_k(const float* __restrict__ S,
                                                const float* __restrict__ z,
                                                __half* __restrict__ Sh,
                                                __half* __restrict__ zh,
                                                const int* __restrict__ causal) {
    const int bh = blockIdx.x;
    const int e = blockIdx.y * 256 + threadIdx.x;
    const int caus = *causal;
    {
        float run = 0.f;
        if (caus) {
            for (int c = 0; c < NCK; c++) {
                size_t idx = ((size_t)bh * NCK + c) * 4096 + e;
                Sh[idx] = __float2half_rn(run);
                run += S[idx];
            }
        } else {
            for (int c = 0; c < NCK; c++) run += S[((size_t)bh * NCK + c) * 4096 + e];
            __half hr = __float2half_rn(run);
            for (int c = 0; c < NCK; c++) Sh[((size_t)bh * NCK + c) * 4096 + e] = hr;
        }
    }
    if (blockIdx.y == 0 && threadIdx.x < 64) {
        int d = threadIdx.x;
        float run = 0.f;
        if (caus) {
            for (int c = 0; c < NCK; c++) {
                size_t idx = ((size_t)bh * NCK + c) * 64 + d;
                zh[idx] = __float2half_rn(run);
                run += z[idx];
            }
        } else {
            for (int c = 0; c < NCK; c++) run += z[((size_t)bh * NCK + c) * 64 + d];
            __half hr = __float2half_rn(run);
            for (int c = 0; c < NCK; c++) zh[((size_t)bh * NCK + c) * 64 + d] = hr;
        }
    }
}

// ---------------------------------------------------------------------------
// Pass 3 (fp16 mma): per-chunk output. Triangular skips + swizzled vT.
// ---------------------------------------------------------------------------
__global__ void __launch_bounds__(256) chunk_out_h(const __half* __restrict__ q,
                                                   const __half* __restrict__ k,
                                                   const __half* __restrict__ v,
                                                   const __half* __restrict__ Sh,
                                                   const __half* __restrict__ zh,
                                                   const int* __restrict__ causal,
                                                   __half* __restrict__ out) {
    extern __shared__ __half smh[];
    __half* qs  = smh + CO_QS;    // [128][72]
    __half* ks  = smh + CO_KS;    // [128][72]
    __half* vT  = smh + CO_VT;    // [64][136] swizzled
    __half* STz = smh + CO_STZ;   // [72][72]
    __half* Ash = smh + CO_AS;    // [128][136]

    const int blk = blockIdx.x;
    const int c = blk & 15, bh = blk >> 4;
    const int b = bh >> 4, h = bh & 15;
    const int tid = threadIdx.x;
    const int lane = tid & 31, warp = tid >> 5;
    const int g = lane >> 2, tg = lane & 3;
    const int caus = *causal;
    const int m0 = warp * 16;

    const size_t base = ((size_t)bh * NSEQ + (size_t)c * CHK) * DD;
    for (int idx = tid; idx < 1024; idx += 256) {
        int i = idx >> 3, d8 = (idx & 7) * 8;
        *(uint4*)&qs[i * 72 + d8] = *(const uint4*)&q[base + (size_t)i * 64 + d8];
        *(uint4*)&ks[i * 72 + d8] = *(const uint4*)&k[base + (size_t)i * 64 + d8];
        uint4 vv = *(const uint4*)&v[base + (size_t)i * 64 + d8];
        const __half* vh = (const __half*)&vv;
#pragma unroll
        for (int j = 0; j < 8; j++) vT[swz136(d8 + j, i)] = vh[j];
    }
    // STz rows 0-63 = S^T (fp16 in global already)
    for (int idx = tid; idx < 512; idx += 256) {
        int j = idx >> 3, d8 = (idx & 7) * 8;
        *(uint4*)&STz[j * 72 + d8] =
            *(const uint4*)&Sh[(size_t)blk * 4096 + (size_t)j * 64 + d8];
    }
    if (tid < 64) STz[64 * 72 + tid] = zh[(size_t)blk * 64 + tid];
    for (int idx = tid; idx < 7 * 72; idx += 256) STz[65 * 72 + idx] = __float2half_rn(0.f);
    __syncthreads();

    const int r0 = m0 + g, r1 = r0 + 8;
    float den0 = 0.f, den1 = 0.f;

    if (caus) {
        const int njmax = 2 * warp + 1;    // tiles nj > njmax are all-zero
#pragma unroll
        for (int h2 = 0; h2 < 2; h2++) {
            if (h2 * 8 <= njmax) {
                float accA[8][4];
#pragma unroll
                for (int nj = 0; nj < 8; nj++)
#pragma unroll
                    for (int x = 0; x < 4; x++) accA[nj][x] = 0.f;
#pragma unroll
                for (int kb = 0; kb < 64; kb += 16) {
                    unsigned a[4];
                    a[0] = *(const unsigned*)&qs[(r0) * 72 + kb + 2 * tg];
                    a[1] = *(const unsigned*)&qs[(r1) * 72 + kb + 2 * tg];
                    a[2] = *(const unsigned*)&qs[(r0) * 72 + kb + 2 * tg + 8];
                    a[3] = *(const unsigned*)&qs[(r1) * 72 + kb + 2 * tg + 8];
#pragma unroll
                    for (int nj = 0; nj < 8; nj++) {
                        int njg = h2 * 8 + nj;
                        if (njg <= njmax) {
                            unsigned bf[2];
                            bf[0] = *(const unsigned*)&ks[(njg * 8 + g) * 72 + kb + 2 * tg];
                            bf[1] = *(const unsigned*)&ks[(njg * 8 + g) * 72 + kb + 2 * tg + 8];
                            mma_f16(accA[nj], a, bf);
                        }
                    }
                }
#pragma unroll
                for (int nj = 0; nj < 8; nj++) {
                    int njg = h2 * 8 + nj;
                    if (njg <= njmax) {
                        int c0 = njg * 8 + 2 * tg;
                        float x00 = (c0     <= r0) ? accA[nj][0] : 0.f;
                        float x01 = (c0 + 1 <= r0) ? accA[nj][1] : 0.f;
                        float x10 = (c0     <= r1) ? accA[nj][2] : 0.f;
                        float x11 = (c0 + 1 <= r1) ? accA[nj][3] : 0.f;
                        den0 += x00 + x01;
                        den1 += x10 + x11;
                        *(__half2*)&Ash[r0 * 136 + c0] = __floats2half2_rn(x00, x01);
                        *(__half2*)&Ash[r1 * 136 + c0] = __floats2half2_rn(x10, x11);
                    }
                }
            }
        }
        den0 += __shfl_xor_sync(0xffffffffu, den0, 1);
        den0 += __shfl_xor_sync(0xffffffffu, den0, 2);
        den1 += __shfl_xor_sync(0xffffffffu, den1, 1);
        den1 += __shfl_xor_sync(0xffffffffu, den1, 2);
        __syncwarp();   // Ash rows are warp-private
    }

    float acc[9][4];
#pragma unroll
    for (int nj = 0; nj < 9; nj++)
#pragma unroll
        for (int x = 0; x < 4; x++) acc[nj][x] = 0.f;

    // q · [S^T | z]  (k-dim = 64)
#pragma unroll
    for (int kb = 0; kb < 64; kb += 16) {
        unsigned a[4];
        a[0] = *(const unsigned*)&qs[(r0) * 72 + kb + 2 * tg];
        a[1] = *(const unsigned*)&qs[(r1) * 72 + kb + 2 * tg];
        a[2] = *(const unsigned*)&qs[(r0) * 72 + kb + 2 * tg + 8];
        a[3] = *(const unsigned*)&qs[(r1) * 72 + kb + 2 * tg + 8];
#pragma unroll
        for (int nj = 0; nj < 9; nj++) {
            unsigned bf[2];
            bf[0] = *(const unsigned*)&STz[(nj * 8 + g) * 72 + kb + 2 * tg];
            bf[1] = *(const unsigned*)&STz[(nj * 8 + g) * 72 + kb + 2 * tg + 8];
            mma_f16(acc[nj], a, bf);
        }
    }
    // A · v  (k-dim = 128): A cols > m0+15 are zero -> only k-tiles kb/16 <= warp
    if (caus) {
#pragma unroll
        for (int kb = 0; kb < 128; kb += 16) {
            if ((kb >> 4) <= warp) {
                const int w0 = kb >> 1;
                unsigned a[4];
                a[0] = *(const unsigned*)&Ash[(r0) * 136 + kb + 2 * tg];
                a[1] = *(const unsigned*)&Ash[(r1) * 136 + kb + 2 * tg];
                a[2] = *(const unsigned*)&Ash[(r0) * 136 + kb + 2 * tg + 8];
                a[3] = *(const unsigned*)&Ash[(r1) * 136 + kb + 2 * tg + 8];
#pragma unroll
                for (int nj = 0; nj < 8; nj++) {
                    int n = nj * 8 + g;
                    unsigned bf[2];
                    bf[0] = *(const unsigned*)&vT[swz136w(n, w0 + tg)];
                    bf[1] = *(const unsigned*)&vT[swz136w(n, w0 + tg + 4)];
                    mma_f16(acc[nj], a, bf);
                }
            }
        }
    }

    float qz0 = __shfl_sync(0xffffffffu, acc[8][0], (lane & ~3));
    float qz1 = __shfl_sync(0xffffffffu, acc[8][2], (lane & ~3));
    float inv0 = 1.f / (den0 + qz0 + EPSV);
    float inv1 = 1.f / (den1 + qz1 + EPSV);

#pragma unroll
    for (int nj = 0; nj < 8; nj++) {
        int col = h * 64 + nj * 8 + 2 * tg;
        size_t o0 = ((size_t)b * NSEQ + (size_t)c * CHK + r0) * EE + col;
        size_t o1 = ((size_t)b * NSEQ + (size_t)c * CHK + r1) * EE + col;
        *(__half2*)&out[o0] = __floats2half2_rn(acc[nj][0] * inv0, acc[nj][1] * inv0);
        *(__half2*)&out[o1] = __floats2half2_rn(acc[nj][2] * inv1, acc[nj][3] * inv1);
    }
}

// ---------------------------------------------------------------------------
extern "C" void kernel_launch(void* const* d_in, const int* in_sizes, int n_in,
                              void* d_out, int out_size) {
    const float* Q  = (const float*)d_in[0];
    const float* K  = (const float*)d_in[1];
    const float* V  = (const float*)d_in[2];
    const float* Wq = (const float*)d_in[3];
    const float* Wk = (const float*)d_in[4];
    const float* Wv = (const float*)d_in[5];
    const float* Wo = (const float*)d_in[6];
    const int* causal = (const int*)d_in[7];
    float* out = (float*)d_out;

    __half *qb, *kb, *vb, *ab, *wh, *xh, *Shb, *zhb;
    float *Sb, *zb;
    cudaGetSymbolAddress((void**)&qb, g_q);
    cudaGetSymbolAddress((void**)&kb, g_k);
    cudaGetSymbolAddress((void**)&vb, g_v);
    cudaGetSymbolAddress((void**)&ab, g_attn);
    cudaGetSymbolAddress((void**)&Sb, g_S);
    cudaGetSymbolAddress((void**)&zb, g_z);
    cudaGetSymbolAddress((void**)&Shb, g_Sh);
    cudaGetSymbolAddress((void**)&zhb, g_zh);
    cudaGetSymbolAddress((void**)&wh, g_wh);
    cudaGetSymbolAddress((void**)&xh, g_xh);

    cudaFuncSetAttribute(gemm_h_qkv, cudaFuncAttributeMaxDynamicSharedMemorySize, GSMEM);
    cudaFuncSetAttribute(gemm_h_out, cudaFuncAttributeMaxDynamicSharedMemorySize, GSMEM);
    cudaFuncSetAttribute(chunk_kv_h, cudaFuncAttributeMaxDynamicSharedMemorySize, KV_SMEM);
    cudaFuncSetAttribute(chunk_out_h, cudaFuncAttributeMaxDynamicSharedMemorySize, CO_SMEM);

    conv_all<<<dim3(4096, 7), 256>>>(Wq, Wk, Wv, Wo, Q, K, V, wh, xh);

    dim3 gq(8, 32, 3);
    gemm_h_qkv<<<gq, 256, GSMEM>>>(xh, wh, qb, kb, vb);

    chunk_kv_h<<<BB * HH * NCK, 256, KV_SMEM>>>(kb, vb, Sb, zb);
    prefix_k<<<dim3(BB * HH, 16), 256>>>(Sb, zb, Shb, zhb, causal);
    chunk_out_h<<<BB * HH * NCK, 256, CO_SMEM>>>(qb, kb, vb, Shb, zhb, causal, ab);

    dim3 go(8, 32);
    gemm_h_out<<<go, 256, GSMEM>>>(ab, wh, out);
}

// round 16
// speedup vs baseline: 1.5255x; 1.0023x over previous
#include <cuda_runtime.h>
#include <cuda_fp16.h>
#include <math.h>
#include <stdint.h>

// Problem constants (fixed by setup_inputs)
#define BB    2
#define HH    16
#define NSEQ  2048
#define EE    1024
#define DD    64
#define CHK   128
#define NCK   16
#define EPSV  1e-6f

// fp16 GEMM tiling: 128x128 CTA tile, BK=64 halves, 3-stage cp.async
#define BKH    64
#define SHSTR  72
#define OP_H   (128 * SHSTR)
#define STG_H  (2 * OP_H)
#define STG_B  (STG_H * 2)
#define NSTG   3
#define GSMEM  (NSTG * STG_B)          // 110592 bytes

// chunk_out smem layout (halves)
#define CO_QS   0                      // [128][72]
#define CO_KS   (CO_QS + 128 * 72)     // [128][72]
#define CO_VT   (CO_KS + 128 * 72)     // [64][136] swizzled
#define CO_STZ  (CO_VT + 64 * 136)     // [72][72]
#define CO_AS   (CO_STZ + 72 * 72)     // [128][136]
#define CO_TOT  (CO_AS + 128 * 136)
#define CO_SMEM (CO_TOT * 2)           // 99456 bytes

// chunk_kv smem (halves): kT [64][136] + vT [64][136], swizzled
#define KV_SMEM (2 * 64 * 136 * 2)

// ---------------- scratch (device globals; no allocation allowed) ----------
__device__ __align__(16) __half g_q[BB*HH*NSEQ*DD];
__device__ __align__(16) __half g_k[BB*HH*NSEQ*DD];
__device__ __align__(16) __half g_v[BB*HH*NSEQ*DD];
__device__ __align__(16) __half g_attn[BB*NSEQ*EE];
__device__ float g_S[BB*HH*NCK*DD*DD];                    // per-chunk KtV, [v][d] fp32
__device__ __align__(16) __half g_Sh[BB*HH*NCK*DD*DD];    // prefixed, fp16
__device__ float g_z[BB*HH*NCK*DD];
__device__ __align__(16) __half g_zh[BB*HH*NCK*DD];
__device__ __align__(16) __half g_wh[4 * EE * EE];
__device__ __align__(16) __half g_xh[3 * BB * NSEQ * EE];

// ---------------------------------------------------------------------------
__device__ __forceinline__ void mma_f16(float c[4], const unsigned a[4], const unsigned b[2]) {
    asm volatile(
        "mma.sync.aligned.m16n8k16.row.col.f32.f16.f16.f32 "
        "{%0,%1,%2,%3}, {%4,%5,%6,%7}, {%8,%9}, {%0,%1,%2,%3};\n"
        : "+f"(c[0]), "+f"(c[1]), "+f"(c[2]), "+f"(c[3])
        : "r"(a[0]), "r"(a[1]), "r"(a[2]), "r"(a[3]), "r"(b[0]), "r"(b[1]));
}

__device__ __forceinline__ void ldsm4(unsigned& r0, unsigned& r1,
                                      unsigned& r2, unsigned& r3, uint32_t addr) {
    asm volatile("ldmatrix.sync.aligned.m8n8.x4.shared.b16 {%0,%1,%2,%3}, [%4];"
                 : "=r"(r0), "=r"(r1), "=r"(r2), "=r"(r3) : "r"(addr));
}

__device__ __forceinline__ void cp16s(uint32_t dst, const void* src) {
    asm volatile("cp.async.cg.shared.global [%0], [%1], 16;\n" :: "r"(dst), "l"(src));
}

// swizzled half index into a [64][136] transposed tile: row d, half-col i
__device__ __forceinline__ int swz136(int d, int i) {
    return d * 136 + (((((i >> 1) ^ ((d >> 3) & 7))) << 1) | (i & 1));
}
// word-aligned variant: row d, word wi (2 halves)
__device__ __forceinline__ int swz136w(int d, int wi) {
    return d * 136 + (((wi) ^ ((d >> 3) & 7)) << 1);
}

// ---------------------------------------------------------------------------
// Fused prepass: fp32 -> fp16 for 4 weights (z=0..3) and 3 inputs (z=4..6).
// grid (4096, 7); weights use only first 1024 x-blocks.
// ---------------------------------------------------------------------------
__global__ void __launch_bounds__(256) conv_all(const float* __restrict__ w0,
                                                const float* __restrict__ w1,
                                                const float* __restrict__ w2,
                                                const float* __restrict__ w3,
                                                const float* __restrict__ x0,
                                                const float* __restrict__ x1,
                                                const float* __restrict__ x2,
                                                __half* __restrict__ wdst,
                                                __half* __restrict__ xdst) {
    const int z = blockIdx.y;
    const float* src;
    __half* d;
    if (z < 4) {
        if (blockIdx.x >= 1024) return;
        src = (z == 0) ? w0 : (z == 1) ? w1 : (z == 2) ? w2 : w3;
        d = wdst + (size_t)z * (EE * EE);
    } else {
        src = (z == 4) ? x0 : (z == 5) ? x1 : x2;
        d = xdst + (size_t)(z - 4) * (BB * NSEQ * EE);
    }
    int i = blockIdx.x * 256 + threadIdx.x;
    float4 v = ((const float4*)src)[i];
    __half2 h0 = __floats2half2_rn(v.x, v.y);
    __half2 h1 = __floats2half2_rn(v.z, v.w);
    ((uint2*)d)[i] = make_uint2(*(unsigned*)&h0, *(unsigned*)&h1);
}

// ---------------------------------------------------------------------------
// Pipelined FP16 NT-GEMM with ldmatrix fragment loads.
// ---------------------------------------------------------------------------
template<bool FMAP, bool BHND>
__device__ __forceinline__ void gemm_h_body(const __half* __restrict__ A,
                                            const __half* __restrict__ W,
                                            void* __restrict__ Cv, __half* sm) {
    const int tid = threadIdx.x, lane = tid & 31, warp = tid >> 5;
    const int bm = blockIdx.y * 128, bn = blockIdx.x * 128;
    const int wm = (warp >> 1) * 32, wn = (warp & 1) * 64;
    const int g = lane >> 2, tg = lane & 3;
    const uint32_t sb = (uint32_t)__cvta_generic_to_shared(sm);

    // ldmatrix lane offsets (in halves)
    const int aoff = ((lane & 7) + (lane & 8)) * SHSTR + ((lane & 16) >> 1);
    const int boff = ((lane & 7) + ((lane & 16) >> 1)) * SHSTR + (lane & 8);

    float acc[2][8][4];
#pragma unroll
    for (int mi = 0; mi < 2; mi++)
#pragma unroll
        for (int nj = 0; nj < 8; nj++)
#pragma unroll
            for (int x = 0; x < 4; x++) acc[mi][nj][x] = 0.f;

    auto issue = [&](int buf, int k0) {
        uint32_t dA = sb + buf * STG_B;
        uint32_t dB = dA + OP_H * 2;
#pragma unroll
        for (int i = 0; i < 4; i++) {
            int l = tid + i * 256;
            int r = l >> 3, c8 = (l & 7) * 8;
            uint32_t so = (uint32_t)(r * SHSTR + c8) * 2;
            cp16s(dA + so, A + (size_t)(bm + r) * 1024 + k0 + c8);
            cp16s(dB + so, W + (size_t)(bn + r) * 1024 + k0 + c8);
        }
    };

    issue(0, 0);
    asm volatile("cp.async.commit_group;" ::: "memory");
    issue(1, BKH);
    asm volatile("cp.async.commit_group;" ::: "memory");

    for (int t = 0; t < 16; t++) {
        asm volatile("cp.async.wait_group 1;" ::: "memory");
        __syncthreads();
        if (t + 2 < 16) issue((t + 2) % NSTG, (t + 2) * BKH);
        asm volatile("cp.async.commit_group;" ::: "memory");

        const uint32_t sA = sb + (t % NSTG) * STG_B;
        const uint32_t sB = sA + OP_H * 2;
#pragma unroll
        for (int ks = 0; ks < 4; ks++) {
            const int kb = ks * 16;
            unsigned a[2][4], b[8][2];
#pragma unroll
            for (int mi = 0; mi < 2; mi++) {
                uint32_t ad = sA + (uint32_t)(((wm + mi * 16) * SHSTR + kb) + aoff) * 2;
                ldsm4(a[mi][0], a[mi][1], a[mi][2], a[mi][3], ad);
            }
#pragma unroll
            for (int p = 0; p < 4; p++) {
                uint32_t bd = sB + (uint32_t)(((wn + p * 16) * SHSTR + kb) + boff) * 2;
                ldsm4(b[2*p][0], b[2*p][1], b[2*p+1][0], b[2*p+1][1], bd);
            }
#pragma unroll
            for (int mi = 0; mi < 2; mi++)
#pragma unroll
                for (int nj = 0; nj < 8; nj++)
                    mma_f16(acc[mi][nj], a[mi], b[nj]);
        }
    }

#pragma unroll
    for (int mi = 0; mi < 2; mi++) {
#pragma unroll
        for (int nj = 0; nj < 8; nj++) {
            int row0 = bm + wm + mi * 16 + g;
            int col0 = bn + wn + nj * 8 + 2 * tg;
#pragma unroll
            for (int half_ = 0; half_ < 2; half_++) {
                int row = row0 + half_ * 8;
                float v0 = acc[mi][nj][half_ * 2 + 0];
                float v1 = acc[mi][nj][half_ * 2 + 1];
                if (FMAP) {
                    v0 = (v0 > 0.f) ? (v0 + 1.f) : expf(v0);
                    v1 = (v1 > 0.f) ? (v1 + 1.f) : expf(v1);
                }
                if (BHND) {
                    int bb = row >> 11, n = row & 2047;
                    int h = col0 >> 6, d = col0 & 63;
                    size_t idx = ((((size_t)bb * HH + h) * NSEQ + n) * DD + d);
                    __half2 hv = __floats2half2_rn(v0, v1);
                    *(__half2*)&((__half*)Cv)[idx] = hv;
                } else {
                    size_t idx = (size_t)row * 1024 + col0;
                    *(float2*)&((float*)Cv)[idx] = make_float2(v0, v1);
                }
            }
        }
    }
}

// K and V projections (512 CTAs): z=0 -> K (fmap), z=1 -> V (no fmap).
__global__ void __launch_bounds__(256, 2) gemm_h_kv(const __half* __restrict__ XH,
                                                    const __half* __restrict__ WH,
                                                    __half* __restrict__ kb,
                                                    __half* __restrict__ vb) {
    extern __shared__ __half smh[];
    const int z = blockIdx.z;                 // 0 -> K, 1 -> V
    const __half* A = XH + (size_t)(z + 1) * (BB * NSEQ * EE);
    const __half* W = WH + (size_t)(z + 1) * (EE * EE);
    if (z == 0) gemm_h_body<true,  true>(A, W, kb, smh);
    else        gemm_h_body<false, true>(A, W, vb, smh);
}

// Q projection (256 CTAs) — overlapped with chunk_kv/prefix on another stream.
__global__ void __launch_bounds__(256, 2) gemm_h_q(const __half* __restrict__ XH,
                                                   const __half* __restrict__ WH,
                                                   __half* __restrict__ qb) {
    extern __shared__ __half smh[];
    gemm_h_body<true, true>(XH, WH, qb, smh);
}

__global__ void __launch_bounds__(256, 2) gemm_h_out(const __half* __restrict__ A,
                                                     const __half* __restrict__ WH,
                                                     float* __restrict__ C) {
    extern __shared__ __half smh[];
    gemm_h_body<false, false>(A, WH + (size_t)3 * EE * EE, C, smh);
}

// ---------------------------------------------------------------------------
// Pass 1 (fp16 mma): ST_c[v][d] = sum_i k[i,d]*v[i,v] (fp32, transposed),
// z_c[d] = sum_i k[i,d]. Swizzled smem transposes (conflict-free).
// ---------------------------------------------------------------------------
__global__ void __launch_bounds__(256) chunk_kv_h(const __half* __restrict__ k,
                                                  const __half* __restrict__ v,
                                                  float* __restrict__ S,
                                                  float* __restrict__ z) {
    extern __shared__ __half smh[];
    __half* kT = smh;              // [64][136] swizzled
    __half* vT = smh + 64 * 136;
    const int blk = blockIdx.x;
    const int c = blk & 15, bh = blk >> 4;
    const int tid = threadIdx.x;
    const int lane = tid & 31, warp = tid >> 5;
    const int g = lane >> 2, tg = lane & 3;

    const size_t base = ((size_t)bh * NSEQ + (size_t)c * CHK) * DD;
    for (int idx = tid; idx < 1024; idx += 256) {
        int i = idx >> 3, d8 = (idx & 7) * 8;
        uint4 kk = *(const uint4*)&k[base + (size_t)i * 64 + d8];
        uint4 vv = *(const uint4*)&v[base + (size_t)i * 64 + d8];
        const __half* kh = (const __half*)&kk;
        const __half* vh = (const __half*)&vv;
#pragma unroll
        for (int j = 0; j < 8; j++) {
            kT[swz136(d8 + j, i)] = kh[j];
            vT[swz136(d8 + j, i)] = vh[j];
        }
    }
    __syncthreads();

    // z: 4 lanes per d, word loads
    {
        int d = tid >> 2, quad = tid & 3;
        float s = 0.f;
#pragma unroll
        for (int wi = 0; wi < 16; wi++) {
            unsigned u = *(const unsigned*)&kT[swz136w(d, quad * 16 + wi)];
            __half2 h = *(__half2*)&u;
            s += __half2float(h.x) + __half2float(h.y);
        }
        s += __shfl_xor_sync(0xffffffffu, s, 1);
        s += __shfl_xor_sync(0xffffffffu, s, 2);
        if (quad == 0) z[(size_t)blk * 64 + d] = s;
    }

    const int wm = (warp & 1) * 32, wn = (warp >> 1) * 16;
    float acc[2][2][4];
#pragma unroll
    for (int mi = 0; mi < 2; mi++)
#pragma unroll
        for (int nj = 0; nj < 2; nj++)
#pragma unroll
            for (int x = 0; x < 4; x++) acc[mi][nj][x] = 0.f;

#pragma unroll
    for (int kb = 0; kb < 128; kb += 16) {
        const int w0 = kb >> 1;    // word base
        unsigned a[2][4], b[2][2];
#pragma unroll
        for (int mi = 0; mi < 2; mi++) {
            int m = wm + mi * 16 + g;
            a[mi][0] = *(const unsigned*)&kT[swz136w(m,     w0 + tg)];
            a[mi][1] = *(const unsigned*)&kT[swz136w(m + 8, w0 + tg)];
            a[mi][2] = *(const unsigned*)&kT[swz136w(m,     w0 + tg + 4)];
            a[mi][3] = *(const unsigned*)&kT[swz136w(m + 8, w0 + tg + 4)];
        }
#pragma unroll
        for (int nj = 0; nj < 2; nj++) {
            int n = wn + nj * 8 + g;
            b[nj][0] = *(const unsigned*)&vT[swz136w(n, w0 + tg)];
            b[nj][1] = *(const unsigned*)&vT[swz136w(n, w0 + tg + 4)];
        }
#pragma unroll
        for (int mi = 0; mi < 2; mi++)
#pragma unroll
            for (int nj = 0; nj < 2; nj++)
                mma_f16(acc[mi][nj], a[mi], b[nj]);
    }

    float* Sc = S + (size_t)blk * 4096;
#pragma unroll
    for (int mi = 0; mi < 2; mi++) {
#pragma unroll
        for (int nj = 0; nj < 2; nj++) {
            int d0 = wm + mi * 16 + g;
            int v0 = wn + nj * 8 + 2 * tg;
            Sc[(v0)     * 64 + d0    ] = acc[mi][nj][0];
            Sc[(v0 + 1) * 64 + d0    ] = acc[mi][nj][1];
            Sc[(v0)     * 64 + d0 + 8] = acc[mi][nj][2];
            Sc[(v0 + 1) * 64 + d0 + 8] = acc[mi][nj][3];
        }
    }
}

// ---------------------------------------------------------------------------
// Pass 2: exclusive prefix (causal) / total (non-causal); fp32 scan in regs,
// fp16 output for chunk_out. grid (32,16).
// ---------------------------------------------------------------------------
__global__ void __launch_bounds__(256) prefix_k(const float* __restrict__ S,
                                                const float* __restrict__ z,
                                                __half* __restrict__ Sh,
                                                __half* __restrict__ zh,
                                                const int* __restrict__ causal) {
    const int bh = blockIdx.x;
    const int e = blockIdx.y * 256 + threadIdx.x;
    const int caus = *causal;
    {
        float run = 0.f;
        if (caus) {
            for (int c = 0; c < NCK; c++) {
                size_t idx = ((size_t)bh * NCK + c) * 4096 + e;
                Sh[idx] = __float2half_rn(run);
                run += S[idx];
            }
        } else {
            for (int c = 0; c < NCK; c++) run += S[((size_t)bh * NCK + c) * 4096 + e];
            __half hr = __float2half_rn(run);
            for (int c = 0; c < NCK; c++) Sh[((size_t)bh * NCK + c) * 4096 + e] = hr;
        }
    }
    if (blockIdx.y == 0 && threadIdx.x < 64) {
        int d = threadIdx.x;
        float run = 0.f;
        if (caus) {
            for (int c = 0; c < NCK; c++) {
                size_t idx = ((size_t)bh * NCK + c) * 64 + d;
                zh[idx] = __float2half_rn(run);
                run += z[idx];
            }
        } else {
            for (int c = 0; c < NCK; c++) run += z[((size_t)bh * NCK + c) * 64 + d];
            __half hr = __float2half_rn(run);
            for (int c = 0; c < NCK; c++) zh[((size_t)bh * NCK + c) * 64 + d] = hr;
        }
    }
}

// ---------------------------------------------------------------------------
// Pass 3 (fp16 mma): per-chunk output. Triangular skips + swizzled vT.
// ---------------------------------------------------------------------------
__global__ void __launch_bounds__(256) chunk_out_h(const __half* __restrict__ q,
                                                   const __half* __restrict__ k,
                                                   const __half* __restrict__ v,
                                                   const __half* __restrict__ Sh,
                                                   const __half* __restrict__ zh,
                                                   const int* __restrict__ causal,
                                                   __half* __restrict__ out) {
    extern __shared__ __half smh[];
    __half* qs  = smh + CO_QS;    // [128][72]
    __half* ks  = smh + CO_KS;    // [128][72]
    __half* vT  = smh + CO_VT;    // [64][136] swizzled
    __half* STz = smh + CO_STZ;   // [72][72]
    __half* Ash = smh + CO_AS;    // [128][136]

    const int blk = blockIdx.x;
    const int c = blk & 15, bh = blk >> 4;
    const int b = bh >> 4, h = bh & 15;
    const int tid = threadIdx.x;
    const int lane = tid & 31, warp = tid >> 5;
    const int g = lane >> 2, tg = lane & 3;
    const int caus = *causal;
    const int m0 = warp * 16;

    const size_t base = ((size_t)bh * NSEQ + (size_t)c * CHK) * DD;
    for (int idx = tid; idx < 1024; idx += 256) {
        int i = idx >> 3, d8 = (idx & 7) * 8;
        *(uint4*)&qs[i * 72 + d8] = *(const uint4*)&q[base + (size_t)i * 64 + d8];
        *(uint4*)&ks[i * 72 + d8] = *(const uint4*)&k[base + (size_t)i * 64 + d8];
        uint4 vv = *(const uint4*)&v[base + (size_t)i * 64 + d8];
        const __half* vh = (const __half*)&vv;
#pragma unroll
        for (int j = 0; j < 8; j++) vT[swz136(d8 + j, i)] = vh[j];
    }
    // STz rows 0-63 = S^T (fp16 in global already)
    for (int idx = tid; idx < 512; idx += 256) {
        int j = idx >> 3, d8 = (idx & 7) * 8;
        *(uint4*)&STz[j * 72 + d8] =
            *(const uint4*)&Sh[(size_t)blk * 4096 + (size_t)j * 64 + d8];
    }
    if (tid < 64) STz[64 * 72 + tid] = zh[(size_t)blk * 64 + tid];
    for (int idx = tid; idx < 7 * 72; idx += 256) STz[65 * 72 + idx] = __float2half_rn(0.f);
    __syncthreads();

    const int r0 = m0 + g, r1 = r0 + 8;
    float den0 = 0.f, den1 = 0.f;

    if (caus) {
        const int njmax = 2 * warp + 1;    // tiles nj > njmax are all-zero
#pragma unroll
        for (int h2 = 0; h2 < 2; h2++) {
            if (h2 * 8 <= njmax) {
                float accA[8][4];
#pragma unroll
                for (int nj = 0; nj < 8; nj++)
#pragma unroll
                    for (int x = 0; x < 4; x++) accA[nj][x] = 0.f;
#pragma unroll
                for (int kb = 0; kb < 64; kb += 16) {
                    unsigned a[4];
                    a[0] = *(const unsigned*)&qs[(r0) * 72 + kb + 2 * tg];
                    a[1] = *(const unsigned*)&qs[(r1) * 72 + kb + 2 * tg];
                    a[2] = *(const unsigned*)&qs[(r0) * 72 + kb + 2 * tg + 8];
                    a[3] = *(const unsigned*)&qs[(r1) * 72 + kb + 2 * tg + 8];
#pragma unroll
                    for (int nj = 0; nj < 8; nj++) {
                        int njg = h2 * 8 + nj;
                        if (njg <= njmax) {
                            unsigned bf[2];
                            bf[0] = *(const unsigned*)&ks[(njg * 8 + g) * 72 + kb + 2 * tg];
                            bf[1] = *(const unsigned*)&ks[(njg * 8 + g) * 72 + kb + 2 * tg + 8];
                            mma_f16(accA[nj], a, bf);
                        }
                    }
                }
#pragma unroll
                for (int nj = 0; nj < 8; nj++) {
                    int njg = h2 * 8 + nj;
                    if (njg <= njmax) {
                        int c0 = njg * 8 + 2 * tg;
                        float x00 = (c0     <= r0) ? accA[nj][0] : 0.f;
                        float x01 = (c0 + 1 <= r0) ? accA[nj][1] : 0.f;
                        float x10 = (c0     <= r1) ? accA[nj][2] : 0.f;
                        float x11 = (c0 + 1 <= r1) ? accA[nj][3] : 0.f;
                        den0 += x00 + x01;
                        den1 += x10 + x11;
                        *(__half2*)&Ash[r0 * 136 + c0] = __floats2half2_rn(x00, x01);
                        *(__half2*)&Ash[r1 * 136 + c0] = __floats2half2_rn(x10, x11);
                    }
                }
            }
        }
        den0 += __shfl_xor_sync(0xffffffffu, den0, 1);
        den0 += __shfl_xor_sync(0xffffffffu, den0, 2);
        den1 += __shfl_xor_sync(0xffffffffu, den1, 1);
        den1 += __shfl_xor_sync(0xffffffffu, den1, 2);
        __syncwarp();   // Ash rows are warp-private
    }

    float acc[9][4];
#pragma unroll
    for (int nj = 0; nj < 9; nj++)
#pragma unroll
        for (int x = 0; x < 4; x++) acc[nj][x] = 0.f;

    // q · [S^T | z]  (k-dim = 64)
#pragma unroll
    for (int kb = 0; kb < 64; kb += 16) {
        unsigned a[4];
        a[0] = *(const unsigned*)&qs[(r0) * 72 + kb + 2 * tg];
        a[1] = *(const unsigned*)&qs[(r1) * 72 + kb + 2 * tg];
        a[2] = *(const unsigned*)&qs[(r0) * 72 + kb + 2 * tg + 8];
        a[3] = *(const unsigned*)&qs[(r1) * 72 + kb + 2 * tg + 8];
#pragma unroll
        for (int nj = 0; nj < 9; nj++) {
            unsigned bf[2];
            bf[0] = *(const unsigned*)&STz[(nj * 8 + g) * 72 + kb + 2 * tg];
            bf[1] = *(const unsigned*)&STz[(nj * 8 + g) * 72 + kb + 2 * tg + 8];
            mma_f16(acc[nj], a, bf);
        }
    }
    // A · v  (k-dim = 128): A cols > m0+15 are zero -> only k-tiles kb/16 <= warp
    if (caus) {
#pragma unroll
        for (int kb = 0; kb < 128; kb += 16) {
            if ((kb >> 4) <= warp) {
                const int w0 = kb >> 1;
                unsigned a[4];
                a[0] = *(const unsigned*)&Ash[(r0) * 136 + kb + 2 * tg];
                a[1] = *(const unsigned*)&Ash[(r1) * 136 + kb + 2 * tg];
                a[2] = *(const unsigned*)&Ash[(r0) * 136 + kb + 2 * tg + 8];
                a[3] = *(const unsigned*)&Ash[(r1) * 136 + kb + 2 * tg + 8];
#pragma unroll
                for (int nj = 0; nj < 8; nj++) {
                    int n = nj * 8 + g;
                    unsigned bf[2];
                    bf[0] = *(const unsigned*)&vT[swz136w(n, w0 + tg)];
                    bf[1] = *(const unsigned*)&vT[swz136w(n, w0 + tg + 4)];
                    mma_f16(acc[nj], a, bf);
                }
            }
        }
    }

    float qz0 = __shfl_sync(0xffffffffu, acc[8][0], (lane & ~3));
    float qz1 = __shfl_sync(0xffffffffu, acc[8][2], (lane & ~3));
    float inv0 = 1.f / (den0 + qz0 + EPSV);
    float inv1 = 1.f / (den1 + qz1 + EPSV);

#pragma unroll
    for (int nj = 0; nj < 8; nj++) {
        int col = h * 64 + nj * 8 + 2 * tg;
        size_t o0 = ((size_t)b * NSEQ + (size_t)c * CHK + r0) * EE + col;
        size_t o1 = ((size_t)b * NSEQ + (size_t)c * CHK + r1) * EE + col;
        *(__half2*)&out[o0] = __floats2half2_rn(acc[nj][0] * inv0, acc[nj][1] * inv0);
        *(__half2*)&out[o1] = __floats2half2_rn(acc[nj][2] * inv1, acc[nj][3] * inv1);
    }
}

// ---------------------------------------------------------------------------
extern "C" void kernel_launch(void* const* d_in, const int* in_sizes, int n_in,
                              void* d_out, int out_size) {
    const float* Q  = (const float*)d_in[0];
    const float* K  = (const float*)d_in[1];
    const float* V  = (const float*)d_in[2];
    const float* Wq = (const float*)d_in[3];
    const float* Wk = (const float*)d_in[4];
    const float* Wv = (const float*)d_in[5];
    const float* Wo = (const float*)d_in[6];
    const int* causal = (const int*)d_in[7];
    float* out = (float*)d_out;

    __half *qb, *kb, *vb, *ab, *wh, *xh, *Shb, *zhb;
    float *Sb, *zb;
    cudaGetSymbolAddress((void**)&qb, g_q);
    cudaGetSymbolAddress((void**)&kb, g_k);
    cudaGetSymbolAddress((void**)&vb, g_v);
    cudaGetSymbolAddress((void**)&ab, g_attn);
    cudaGetSymbolAddress((void**)&Sb, g_S);
    cudaGetSymbolAddress((void**)&zb, g_z);
    cudaGetSymbolAddress((void**)&Shb, g_Sh);
    cudaGetSymbolAddress((void**)&zhb, g_zh);
    cudaGetSymbolAddress((void**)&wh, g_wh);
    cudaGetSymbolAddress((void**)&xh, g_xh);

    cudaFuncSetAttribute(gemm_h_kv,  cudaFuncAttributeMaxDynamicSharedMemorySize, GSMEM);
    cudaFuncSetAttribute(gemm_h_q,   cudaFuncAttributeMaxDynamicSharedMemorySize, GSMEM);
    cudaFuncSetAttribute(gemm_h_out, cudaFuncAttributeMaxDynamicSharedMemorySize, GSMEM);
    cudaFuncSetAttribute(chunk_kv_h, cudaFuncAttributeMaxDynamicSharedMemorySize, KV_SMEM);
    cudaFuncSetAttribute(chunk_out_h, cudaFuncAttributeMaxDynamicSharedMemorySize, CO_SMEM);

    // fork/join resources (host objects; not destroyed because destroying a
    // stream/event mid-capture invalidates the capture; kernel_launch is only
    // invoked a handful of times)
    cudaStream_t s2;
    cudaEvent_t ev1, ev2;
    cudaStreamCreateWithFlags(&s2, cudaStreamNonBlocking);
    cudaEventCreateWithFlags(&ev1, cudaEventDisableTiming);
    cudaEventCreateWithFlags(&ev2, cudaEventDisableTiming);

    conv_all<<<dim3(4096, 7), 256>>>(Wq, Wk, Wv, Wo, Q, K, V, wh, xh);

    // K,V projections on the main stream
    gemm_h_kv<<<dim3(8, 32, 2), 256, GSMEM>>>(xh, wh, kb, vb);

    // fork: Q projection runs concurrently with chunk_kv + prefix
    cudaEventRecord(ev1, 0);
    cudaStreamWaitEvent(s2, ev1, 0);
    gemm_h_q<<<dim3(8, 32), 256, GSMEM, s2>>>(xh, wh, qb);

    chunk_kv_h<<<BB * HH * NCK, 256, KV_SMEM>>>(kb, vb, Sb, zb);
    prefix_k<<<dim3(BB * HH, 16), 256>>>(Sb, zb, Shb, zhb, causal);

    // join: chunk_out needs q as well
    cudaEventRecord(ev2, s2);
    cudaStreamWaitEvent(0, ev2, 0);

    chunk_out_h<<<BB * HH * NCK, 256, CO_SMEM>>>(qb, kb, vb, Shb, zhb, causal, ab);

    dim3 go(8, 32);
    gemm_h_out<<<go, 256, GSMEM>>>(ab, wh, out);
}

// round 17
// speedup vs baseline: 1.5266x; 1.0007x over previous
#include <cuda_runtime.h>
#include <cuda_fp16.h>
#include <math.h>
#include <stdint.h>

// Problem constants (fixed by setup_inputs)
#define BB    2
#define HH    16
#define NSEQ  2048
#define EE    1024
#define DD    64
#define CHK   128
#define NCK   16
#define EPSV  1e-6f

// fp16 GEMM tiling: 128x128 CTA tile, BK=64 halves, 3-stage cp.async
#define BKH    64
#define SHSTR  72
#define OP_H   (128 * SHSTR)
#define STG_H  (2 * OP_H)
#define STG_B  (STG_H * 2)
#define NSTG   3
#define GSMEM  (NSTG * STG_B)          // 110592 bytes

// chunk_out smem layout (halves), plus 128 floats of den after CO_TOT
#define CO_QS   0                      // [128][72]
#define CO_KS   (CO_QS + 128 * 72)     // [128][72]
#define CO_VT   (CO_KS + 128 * 72)     // [64][136] swizzled
#define CO_STZ  (CO_VT + 64 * 136)     // [72][72]
#define CO_AS   (CO_STZ + 72 * 72)     // [128][136]
#define CO_TOT  (CO_AS + 128 * 136)
#define CO_SMEM (CO_TOT * 2 + 512)     // + dens[128] fp32

// chunk_kv smem (halves): kT [64][136] + vT [64][136], swizzled
#define KV_SMEM (2 * 64 * 136 * 2)

// ---------------- scratch (device globals; no allocation allowed) ----------
__device__ __align__(16) __half g_q[BB*HH*NSEQ*DD];
__device__ __align__(16) __half g_k[BB*HH*NSEQ*DD];
__device__ __align__(16) __half g_v[BB*HH*NSEQ*DD];
__device__ __align__(16) __half g_attn[BB*NSEQ*EE];
__device__ float g_S[BB*HH*NCK*DD*DD];                    // per-chunk KtV, [v][d] fp32
__device__ __align__(16) __half g_Sh[BB*HH*NCK*DD*DD];    // prefixed, fp16
__device__ float g_z[BB*HH*NCK*DD];
__device__ __align__(16) __half g_zh[BB*HH*NCK*DD];
__device__ __align__(16) __half g_wh[4 * EE * EE];
__device__ __align__(16) __half g_xh[3 * BB * NSEQ * EE];

// ---------------------------------------------------------------------------
__device__ __forceinline__ void mma_f16(float c[4], const unsigned a[4], const unsigned b[2]) {
    asm volatile(
        "mma.sync.aligned.m16n8k16.row.col.f32.f16.f16.f32 "
        "{%0,%1,%2,%3}, {%4,%5,%6,%7}, {%8,%9}, {%0,%1,%2,%3};\n"
        : "+f"(c[0]), "+f"(c[1]), "+f"(c[2]), "+f"(c[3])
        : "r"(a[0]), "r"(a[1]), "r"(a[2]), "r"(a[3]), "r"(b[0]), "r"(b[1]));
}

__device__ __forceinline__ void ldsm4(unsigned& r0, unsigned& r1,
                                      unsigned& r2, unsigned& r3, uint32_t addr) {
    asm volatile("ldmatrix.sync.aligned.m8n8.x4.shared.b16 {%0,%1,%2,%3}, [%4];"
                 : "=r"(r0), "=r"(r1), "=r"(r2), "=r"(r3) : "r"(addr));
}

__device__ __forceinline__ void cp16s(uint32_t dst, const void* src) {
    asm volatile("cp.async.cg.shared.global [%0], [%1], 16;\n" :: "r"(dst), "l"(src));
}

// swizzled half index into a [64][136] transposed tile: row d, half-col i
__device__ __forceinline__ int swz136(int d, int i) {
    return d * 136 + (((((i >> 1) ^ ((d >> 3) & 7))) << 1) | (i & 1));
}
// word-aligned variant: row d, word wi (2 halves)
__device__ __forceinline__ int swz136w(int d, int wi) {
    return d * 136 + (((wi) ^ ((d >> 3) & 7)) << 1);
}

// ---------------------------------------------------------------------------
// Fused prepass: fp32 -> fp16 for 4 weights (z=0..3) and 3 inputs (z=4..6).
// ---------------------------------------------------------------------------
__global__ void __launch_bounds__(256) conv_all(const float* __restrict__ w0,
                                                const float* __restrict__ w1,
                                                const float* __restrict__ w2,
                                                const float* __restrict__ w3,
                                                const float* __restrict__ x0,
                                                const float* __restrict__ x1,
                                                const float* __restrict__ x2,
                                                __half* __restrict__ wdst,
                                                __half* __restrict__ xdst) {
    const int z = blockIdx.y;
    const float* src;
    __half* d;
    if (z < 4) {
        if (blockIdx.x >= 1024) return;
        src = (z == 0) ? w0 : (z == 1) ? w1 : (z == 2) ? w2 : w3;
        d = wdst + (size_t)z * (EE * EE);
    } else {
        src = (z == 4) ? x0 : (z == 5) ? x1 : x2;
        d = xdst + (size_t)(z - 4) * (BB * NSEQ * EE);
    }
    int i = blockIdx.x * 256 + threadIdx.x;
    float4 v = ((const float4*)src)[i];
    __half2 h0 = __floats2half2_rn(v.x, v.y);
    __half2 h1 = __floats2half2_rn(v.z, v.w);
    ((uint2*)d)[i] = make_uint2(*(unsigned*)&h0, *(unsigned*)&h1);
}

// ---------------------------------------------------------------------------
// Pipelined FP16 NT-GEMM with ldmatrix fragment loads.
// ---------------------------------------------------------------------------
template<bool FMAP, bool BHND>
__device__ __forceinline__ void gemm_h_body(const __half* __restrict__ A,
                                            const __half* __restrict__ W,
                                            void* __restrict__ Cv, __half* sm) {
    const int tid = threadIdx.x, lane = tid & 31, warp = tid >> 5;
    const int bm = blockIdx.y * 128, bn = blockIdx.x * 128;
    const int wm = (warp >> 1) * 32, wn = (warp & 1) * 64;
    const int g = lane >> 2, tg = lane & 3;
    const uint32_t sb = (uint32_t)__cvta_generic_to_shared(sm);

    const int aoff = ((lane & 7) + (lane & 8)) * SHSTR + ((lane & 16) >> 1);
    const int boff = ((lane & 7) + ((lane & 16) >> 1)) * SHSTR + (lane & 8);

    float acc[2][8][4];
#pragma unroll
    for (int mi = 0; mi < 2; mi++)
#pragma unroll
        for (int nj = 0; nj < 8; nj++)
#pragma unroll
            for (int x = 0; x < 4; x++) acc[mi][nj][x] = 0.f;

    auto issue = [&](int buf, int k0) {
        uint32_t dA = sb + buf * STG_B;
        uint32_t dB = dA + OP_H * 2;
#pragma unroll
        for (int i = 0; i < 4; i++) {
            int l = tid + i * 256;
            int r = l >> 3, c8 = (l & 7) * 8;
            uint32_t so = (uint32_t)(r * SHSTR + c8) * 2;
            cp16s(dA + so, A + (size_t)(bm + r) * 1024 + k0 + c8);
            cp16s(dB + so, W + (size_t)(bn + r) * 1024 + k0 + c8);
        }
    };

    issue(0, 0);
    asm volatile("cp.async.commit_group;" ::: "memory");
    issue(1, BKH);
    asm volatile("cp.async.commit_group;" ::: "memory");

    for (int t = 0; t < 16; t++) {
        asm volatile("cp.async.wait_group 1;" ::: "memory");
        __syncthreads();
        if (t + 2 < 16) issue((t + 2) % NSTG, (t + 2) * BKH);
        asm volatile("cp.async.commit_group;" ::: "memory");

        const uint32_t sA = sb + (t % NSTG) * STG_B;
        const uint32_t sB = sA + OP_H * 2;
#pragma unroll
        for (int ks = 0; ks < 4; ks++) {
            const int kb = ks * 16;
            unsigned a[2][4], b[8][2];
#pragma unroll
            for (int mi = 0; mi < 2; mi++) {
                uint32_t ad = sA + (uint32_t)(((wm + mi * 16) * SHSTR + kb) + aoff) * 2;
                ldsm4(a[mi][0], a[mi][1], a[mi][2], a[mi][3], ad);
            }
#pragma unroll
            for (int p = 0; p < 4; p++) {
                uint32_t bd = sB + (uint32_t)(((wn + p * 16) * SHSTR + kb) + boff) * 2;
                ldsm4(b[2*p][0], b[2*p][1], b[2*p+1][0], b[2*p+1][1], bd);
            }
#pragma unroll
            for (int mi = 0; mi < 2; mi++)
#pragma unroll
                for (int nj = 0; nj < 8; nj++)
                    mma_f16(acc[mi][nj], a[mi], b[nj]);
        }
    }

#pragma unroll
    for (int mi = 0; mi < 2; mi++) {
#pragma unroll
        for (int nj = 0; nj < 8; nj++) {
            int row0 = bm + wm + mi * 16 + g;
            int col0 = bn + wn + nj * 8 + 2 * tg;
#pragma unroll
            for (int half_ = 0; half_ < 2; half_++) {
                int row = row0 + half_ * 8;
                float v0 = acc[mi][nj][half_ * 2 + 0];
                float v1 = acc[mi][nj][half_ * 2 + 1];
                if (FMAP) {
                    v0 = (v0 > 0.f) ? (v0 + 1.f) : expf(v0);
                    v1 = (v1 > 0.f) ? (v1 + 1.f) : expf(v1);
                }
                if (BHND) {
                    int bb = row >> 11, n = row & 2047;
                    int h = col0 >> 6, d = col0 & 63;
                    size_t idx = ((((size_t)bb * HH + h) * NSEQ + n) * DD + d);
                    __half2 hv = __floats2half2_rn(v0, v1);
                    *(__half2*)&((__half*)Cv)[idx] = hv;
                } else {
                    size_t idx = (size_t)row * 1024 + col0;
                    *(float2*)&((float*)Cv)[idx] = make_float2(v0, v1);
                }
            }
        }
    }
}

// K and V projections (512 CTAs): z=0 -> K (fmap), z=1 -> V (no fmap).
__global__ void __launch_bounds__(256, 2) gemm_h_kv(const __half* __restrict__ XH,
                                                    const __half* __restrict__ WH,
                                                    __half* __restrict__ kb,
                                                    __half* __restrict__ vb) {
    extern __shared__ __half smh[];
    const int z = blockIdx.z;
    const __half* A = XH + (size_t)(z + 1) * (BB * NSEQ * EE);
    const __half* W = WH + (size_t)(z + 1) * (EE * EE);
    if (z == 0) gemm_h_body<true,  true>(A, W, kb, smh);
    else        gemm_h_body<false, true>(A, W, vb, smh);
}

// Q projection (256 CTAs) — overlapped with chunk_kv/prefix on another stream.
__global__ void __launch_bounds__(256, 2) gemm_h_q(const __half* __restrict__ XH,
                                                   const __half* __restrict__ WH,
                                                   __half* __restrict__ qb) {
    extern __shared__ __half smh[];
    gemm_h_body<true, true>(XH, WH, qb, smh);
}

__global__ void __launch_bounds__(256, 2) gemm_h_out(const __half* __restrict__ A,
                                                     const __half* __restrict__ WH,
                                                     float* __restrict__ C) {
    extern __shared__ __half smh[];
    gemm_h_body<false, false>(A, WH + (size_t)3 * EE * EE, C, smh);
}

// ---------------------------------------------------------------------------
// Pass 1 (fp16 mma): ST_c[v][d] = sum_i k[i,d]*v[i,v] (fp32, transposed),
// z_c[d] = sum_i k[i,d]. Swizzled smem transposes (conflict-free).
// ---------------------------------------------------------------------------
__global__ void __launch_bounds__(256) chunk_kv_h(const __half* __restrict__ k,
                                                  const __half* __restrict__ v,
                                                  float* __restrict__ S,
                                                  float* __restrict__ z) {
    extern __shared__ __half smh[];
    __half* kT = smh;              // [64][136] swizzled
    __half* vT = smh + 64 * 136;
    const int blk = blockIdx.x;
    const int c = blk & 15, bh = blk >> 4;
    const int tid = threadIdx.x;
    const int lane = tid & 31, warp = tid >> 5;
    const int g = lane >> 2, tg = lane & 3;

    const size_t base = ((size_t)bh * NSEQ + (size_t)c * CHK) * DD;
    for (int idx = tid; idx < 1024; idx += 256) {
        int i = idx >> 3, d8 = (idx & 7) * 8;
        uint4 kk = *(const uint4*)&k[base + (size_t)i * 64 + d8];
        uint4 vv = *(const uint4*)&v[base + (size_t)i * 64 + d8];
        const __half* kh = (const __half*)&kk;
        const __half* vh = (const __half*)&vv;
#pragma unroll
        for (int j = 0; j < 8; j++) {
            kT[swz136(d8 + j, i)] = kh[j];
            vT[swz136(d8 + j, i)] = vh[j];
        }
    }
    __syncthreads();

    {
        int d = tid >> 2, quad = tid & 3;
        float s = 0.f;
#pragma unroll
        for (int wi = 0; wi < 16; wi++) {
            unsigned u = *(const unsigned*)&kT[swz136w(d, quad * 16 + wi)];
            __half2 h = *(__half2*)&u;
            s += __half2float(h.x) + __half2float(h.y);
        }
        s += __shfl_xor_sync(0xffffffffu, s, 1);
        s += __shfl_xor_sync(0xffffffffu, s, 2);
        if (quad == 0) z[(size_t)blk * 64 + d] = s;
    }

    const int wm = (warp & 1) * 32, wn = (warp >> 1) * 16;
    float acc[2][2][4];
#pragma unroll
    for (int mi = 0; mi < 2; mi++)
#pragma unroll
        for (int nj = 0; nj < 2; nj++)
#pragma unroll
            for (int x = 0; x < 4; x++) acc[mi][nj][x] = 0.f;

#pragma unroll
    for (int kb = 0; kb < 128; kb += 16) {
        const int w0 = kb >> 1;
        unsigned a[2][4], b[2][2];
#pragma unroll
        for (int mi = 0; mi < 2; mi++) {
            int m = wm + mi * 16 + g;
            a[mi][0] = *(const unsigned*)&kT[swz136w(m,     w0 + tg)];
            a[mi][1] = *(const unsigned*)&kT[swz136w(m + 8, w0 + tg)];
            a[mi][2] = *(const unsigned*)&kT[swz136w(m,     w0 + tg + 4)];
            a[mi][3] = *(const unsigned*)&kT[swz136w(m + 8, w0 + tg + 4)];
        }
#pragma unroll
        for (int nj = 0; nj < 2; nj++) {
            int n = wn + nj * 8 + g;
            b[nj][0] = *(const unsigned*)&vT[swz136w(n, w0 + tg)];
            b[nj][1] = *(const unsigned*)&vT[swz136w(n, w0 + tg + 4)];
        }
#pragma unroll
        for (int mi = 0; mi < 2; mi++)
#pragma unroll
            for (int nj = 0; nj < 2; nj++)
                mma_f16(acc[mi][nj], a[mi], b[nj]);
    }

    float* Sc = S + (size_t)blk * 4096;
#pragma unroll
    for (int mi = 0; mi < 2; mi++) {
#pragma unroll
        for (int nj = 0; nj < 2; nj++) {
            int d0 = wm + mi * 16 + g;
            int v0 = wn + nj * 8 + 2 * tg;
            Sc[(v0)     * 64 + d0    ] = acc[mi][nj][0];
            Sc[(v0 + 1) * 64 + d0    ] = acc[mi][nj][1];
            Sc[(v0)     * 64 + d0 + 8] = acc[mi][nj][2];
            Sc[(v0 + 1) * 64 + d0 + 8] = acc[mi][nj][3];
        }
    }
}

// ---------------------------------------------------------------------------
// Pass 2: exclusive prefix (causal) / total (non-causal).
// ---------------------------------------------------------------------------
__global__ void __launch_bounds__(256) prefix_k(const float* __restrict__ S,
                                                const float* __restrict__ z,
                                                __half* __restrict__ Sh,
                                                __half* __restrict__ zh,
                                                const int* __restrict__ causal) {
    const int bh = blockIdx.x;
    const int e = blockIdx.y * 256 + threadIdx.x;
    const int caus = *causal;
    {
        float run = 0.f;
        if (caus) {
            for (int c = 0; c < NCK; c++) {
                size_t idx = ((size_t)bh * NCK + c) * 4096 + e;
                Sh[idx] = __float2half_rn(run);
                run += S[idx];
            }
        } else {
            for (int c = 0; c < NCK; c++) run += S[((size_t)bh * NCK + c) * 4096 + e];
            __half hr = __float2half_rn(run);
            for (int c = 0; c < NCK; c++) Sh[((size_t)bh * NCK + c) * 4096 + e] = hr;
        }
    }
    if (blockIdx.y == 0 && threadIdx.x < 64) {
        int d = threadIdx.x;
        float run = 0.f;
        if (caus) {
            for (int c = 0; c < NCK; c++) {
                size_t idx = ((size_t)bh * NCK + c) * 64 + d;
                zh[idx] = __float2half_rn(run);
                run += z[idx];
            }
        } else {
            for (int c = 0; c < NCK; c++) run += z[((size_t)bh * NCK + c) * 64 + d];
            __half hr = __float2half_rn(run);
            for (int c = 0; c < NCK; c++) zh[((size_t)bh * NCK + c) * 64 + d] = hr;
        }
    }
}

// ---------------------------------------------------------------------------
// Pass 3 (fp16 mma): per-chunk output, WORK-BALANCED:
//   phase 1: warp w computes masked A (GEMM1) for row tile w   (8w+8 mma)
//   phase 2: warp w computes GEMM2 for row tile 7-w            (36+64-8w mma)
// -> 108 mma per warp, uniform. den passed via smem.
// ---------------------------------------------------------------------------
__global__ void __launch_bounds__(256) chunk_out_h(const __half* __restrict__ q,
                                                   const __half* __restrict__ k,
                                                   const __half* __restrict__ v,
                                                   const __half* __restrict__ Sh,
                                                   const __half* __restrict__ zh,
                                                   const int* __restrict__ causal,
                                                   __half* __restrict__ out) {
    extern __shared__ __half smh[];
    __half* qs  = smh + CO_QS;    // [128][72]
    __half* ks  = smh + CO_KS;    // [128][72]
    __half* vT  = smh + CO_VT;    // [64][136] swizzled
    __half* STz = smh + CO_STZ;   // [72][72]
    __half* Ash = smh + CO_AS;    // [128][136]
    float* dens = (float*)(smh + CO_TOT);  // [128]

    const int blk = blockIdx.x;
    const int c = blk & 15, bh = blk >> 4;
    const int b = bh >> 4, h = bh & 15;
    const int tid = threadIdx.x;
    const int lane = tid & 31, warp = tid >> 5;
    const int g = lane >> 2, tg = lane & 3;
    const int caus = *causal;

    const size_t base = ((size_t)bh * NSEQ + (size_t)c * CHK) * DD;
    for (int idx = tid; idx < 1024; idx += 256) {
        int i = idx >> 3, d8 = (idx & 7) * 8;
        *(uint4*)&qs[i * 72 + d8] = *(const uint4*)&q[base + (size_t)i * 64 + d8];
        *(uint4*)&ks[i * 72 + d8] = *(const uint4*)&k[base + (size_t)i * 64 + d8];
        uint4 vv = *(const uint4*)&v[base + (size_t)i * 64 + d8];
        const __half* vh = (const __half*)&vv;
#pragma unroll
        for (int j = 0; j < 8; j++) vT[swz136(d8 + j, i)] = vh[j];
    }
    for (int idx = tid; idx < 512; idx += 256) {
        int j = idx >> 3, d8 = (idx & 7) * 8;
        *(uint4*)&STz[j * 72 + d8] =
            *(const uint4*)&Sh[(size_t)blk * 4096 + (size_t)j * 64 + d8];
    }
    if (tid < 64) STz[64 * 72 + tid] = zh[(size_t)blk * 64 + tid];
    for (int idx = tid; idx < 7 * 72; idx += 256) STz[65 * 72 + idx] = __float2half_rn(0.f);
    __syncthreads();

    // ---- phase 1: GEMM1 for row tile mt1 = warp ----
    if (caus) {
        const int p0 = warp * 16 + g, p1 = p0 + 8;
        float den0 = 0.f, den1 = 0.f;
        const int njmax = 2 * warp + 1;
#pragma unroll
        for (int h2 = 0; h2 < 2; h2++) {
            if (h2 * 8 <= njmax) {
                float accA[8][4];
#pragma unroll
                for (int nj = 0; nj < 8; nj++)
#pragma unroll
                    for (int x = 0; x < 4; x++) accA[nj][x] = 0.f;
#pragma unroll
                for (int kb = 0; kb < 64; kb += 16) {
                    unsigned a[4];
                    a[0] = *(const unsigned*)&qs[(p0) * 72 + kb + 2 * tg];
                    a[1] = *(const unsigned*)&qs[(p1) * 72 + kb + 2 * tg];
                    a[2] = *(const unsigned*)&qs[(p0) * 72 + kb + 2 * tg + 8];
                    a[3] = *(const unsigned*)&qs[(p1) * 72 + kb + 2 * tg + 8];
#pragma unroll
                    for (int nj = 0; nj < 8; nj++) {
                        int njg = h2 * 8 + nj;
                        if (njg <= njmax) {
                            unsigned bf[2];
                            bf[0] = *(const unsigned*)&ks[(njg * 8 + g) * 72 + kb + 2 * tg];
                            bf[1] = *(const unsigned*)&ks[(njg * 8 + g) * 72 + kb + 2 * tg + 8];
                            mma_f16(accA[nj], a, bf);
                        }
                    }
                }
#pragma unroll
                for (int nj = 0; nj < 8; nj++) {
                    int njg = h2 * 8 + nj;
                    if (njg <= njmax) {
                        int c0 = njg * 8 + 2 * tg;
                        float x00 = (c0     <= p0) ? accA[nj][0] : 0.f;
                        float x01 = (c0 + 1 <= p0) ? accA[nj][1] : 0.f;
                        float x10 = (c0     <= p1) ? accA[nj][2] : 0.f;
                        float x11 = (c0 + 1 <= p1) ? accA[nj][3] : 0.f;
                        den0 += x00 + x01;
                        den1 += x10 + x11;
                        *(__half2*)&Ash[p0 * 136 + c0] = __floats2half2_rn(x00, x01);
                        *(__half2*)&Ash[p1 * 136 + c0] = __floats2half2_rn(x10, x11);
                    }
                }
            }
        }
        den0 += __shfl_xor_sync(0xffffffffu, den0, 1);
        den0 += __shfl_xor_sync(0xffffffffu, den0, 2);
        den1 += __shfl_xor_sync(0xffffffffu, den1, 1);
        den1 += __shfl_xor_sync(0xffffffffu, den1, 2);
        if (tg == 0) { dens[p0] = den0; dens[p1] = den1; }
    }
    __syncthreads();   // hand off Ash + dens across warps

    // ---- phase 2: GEMM2 for complementary row tile mt2 = 7 - warp ----
    const int mt2 = 7 - warp;
    const int r0 = mt2 * 16 + g, r1 = r0 + 8;

    float acc[9][4];
#pragma unroll
    for (int nj = 0; nj < 9; nj++)
#pragma unroll
        for (int x = 0; x < 4; x++) acc[nj][x] = 0.f;

    // q · [S^T | z]  (k-dim = 64)
#pragma unroll
    for (int kb = 0; kb < 64; kb += 16) {
        unsigned a[4];
        a[0] = *(const unsigned*)&qs[(r0) * 72 + kb + 2 * tg];
        a[1] = *(const unsigned*)&qs[(r1) * 72 + kb + 2 * tg];
        a[2] = *(const unsigned*)&qs[(r0) * 72 + kb + 2 * tg + 8];
        a[3] = *(const unsigned*)&qs[(r1) * 72 + kb + 2 * tg + 8];
#pragma unroll
        for (int nj = 0; nj < 9; nj++) {
            unsigned bf[2];
            bf[0] = *(const unsigned*)&STz[(nj * 8 + g) * 72 + kb + 2 * tg];
            bf[1] = *(const unsigned*)&STz[(nj * 8 + g) * 72 + kb + 2 * tg + 8];
            mma_f16(acc[nj], a, bf);
        }
    }
    // A · v : rows in tile mt2 need k-tiles kb/16 <= mt2
    if (caus) {
#pragma unroll
        for (int kb = 0; kb < 128; kb += 16) {
            if ((kb >> 4) <= mt2) {
                const int w0 = kb >> 1;
                unsigned a[4];
                a[0] = *(const unsigned*)&Ash[(r0) * 136 + kb + 2 * tg];
                a[1] = *(const unsigned*)&Ash[(r1) * 136 + kb + 2 * tg];
                a[2] = *(const unsigned*)&Ash[(r0) * 136 + kb + 2 * tg + 8];
                a[3] = *(const unsigned*)&Ash[(r1) * 136 + kb + 2 * tg + 8];
#pragma unroll
                for (int nj = 0; nj < 8; nj++) {
                    int n = nj * 8 + g;
                    unsigned bf[2];
                    bf[0] = *(const unsigned*)&vT[swz136w(n, w0 + tg)];
                    bf[1] = *(const unsigned*)&vT[swz136w(n, w0 + tg + 4)];
                    mma_f16(acc[nj], a, bf);
                }
            }
        }
    }

    float d0 = caus ? dens[r0] : 0.f;
    float d1 = caus ? dens[r1] : 0.f;
    float qz0 = __shfl_sync(0xffffffffu, acc[8][0], (lane & ~3));
    float qz1 = __shfl_sync(0xffffffffu, acc[8][2], (lane & ~3));
    float inv0 = 1.f / (d0 + qz0 + EPSV);
    float inv1 = 1.f / (d1 + qz1 + EPSV);

#pragma unroll
    for (int nj = 0; nj < 8; nj++) {
        int col = h * 64 + nj * 8 + 2 * tg;
        size_t o0 = ((size_t)b * NSEQ + (size_t)c * CHK + r0) * EE + col;
        size_t o1 = ((size_t)b * NSEQ + (size_t)c * CHK + r1) * EE + col;
        *(__half2*)&out[o0] = __floats2half2_rn(acc[nj][0] * inv0, acc[nj][1] * inv0);
        *(__half2*)&out[o1] = __floats2half2_rn(acc[nj][2] * inv1, acc[nj][3] * inv1);
    }
}

// ---------------------------------------------------------------------------
extern "C" void kernel_launch(void* const* d_in, const int* in_sizes, int n_in,
                              void* d_out, int out_size) {
    const float* Q  = (const float*)d_in[0];
    const float* K  = (const float*)d_in[1];
    const float* V  = (const float*)d_in[2];
    const float* Wq = (const float*)d_in[3];
    const float* Wk = (const float*)d_in[4];
    const float* Wv = (const float*)d_in[5];
    const float* Wo = (const float*)d_in[6];
    const int* causal = (const int*)d_in[7];
    float* out = (float*)d_out;

    __half *qb, *kb, *vb, *ab, *wh, *xh, *Shb, *zhb;
    float *Sb, *zb;
    cudaGetSymbolAddress((void**)&qb, g_q);
    cudaGetSymbolAddress((void**)&kb, g_k);
    cudaGetSymbolAddress((void**)&vb, g_v);
    cudaGetSymbolAddress((void**)&ab, g_attn);
    cudaGetSymbolAddress((void**)&Sb, g_S);
    cudaGetSymbolAddress((void**)&zb, g_z);
    cudaGetSymbolAddress((void**)&Shb, g_Sh);
    cudaGetSymbolAddress((void**)&zhb, g_zh);
    cudaGetSymbolAddress((void**)&wh, g_wh);
    cudaGetSymbolAddress((void**)&xh, g_xh);

    cudaFuncSetAttribute(gemm_h_kv,  cudaFuncAttributeMaxDynamicSharedMemorySize, GSMEM);
    cudaFuncSetAttribute(gemm_h_q,   cudaFuncAttributeMaxDynamicSharedMemorySize, GSMEM);
    cudaFuncSetAttribute(gemm_h_out, cudaFuncAttributeMaxDynamicSharedMemorySize, GSMEM);
    cudaFuncSetAttribute(chunk_kv_h, cudaFuncAttributeMaxDynamicSharedMemorySize, KV_SMEM);
    cudaFuncSetAttribute(chunk_out_h, cudaFuncAttributeMaxDynamicSharedMemorySize, CO_SMEM);

    cudaStream_t s2;
    cudaEvent_t ev1, ev2;
    cudaStreamCreateWithFlags(&s2, cudaStreamNonBlocking);
    cudaEventCreateWithFlags(&ev1, cudaEventDisableTiming);
    cudaEventCreateWithFlags(&ev2, cudaEventDisableTiming);

    conv_all<<<dim3(4096, 7), 256>>>(Wq, Wk, Wv, Wo, Q, K, V, wh, xh);

    gemm_h_kv<<<dim3(8, 32, 2), 256, GSMEM>>>(xh, wh, kb, vb);

    cudaEventRecord(ev1, 0);
    cudaStreamWaitEvent(s2, ev1, 0);
    gemm_h_q<<<dim3(8, 32), 256, GSMEM, s2>>>(xh, wh, qb);

    chunk_kv_h<<<BB * HH * NCK, 256, KV_SMEM>>>(kb, vb, Sb, zb);
    prefix_k<<<dim3(BB * HH, 16), 256>>>(Sb, zb, Shb, zhb, causal);

    cudaEventRecord(ev2, s2);
    cudaStreamWaitEvent(0, ev2, 0);

    chunk_out_h<<<BB * HH * NCK, 256, CO_SMEM>>>(qb, kb, vb, Shb, zhb, causal, ab);

    dim3 go(8, 32);
    gemm_h_out<<<go, 256, GSMEM>>>(ab, wh, out);
}